// round 2
// baseline (speedup 1.0000x reference)
#include <cuda_runtime.h>
#include <cuda_bf16.h>
#include <math.h>
#include <stdint.h>

// Problem constants
#define TT   8192
#define HH   2048
#define EE   32
#define TOPK 8
#define II   1024
#define ISH  2048   // NSH * I

// ---------------------------------------------------------------------------
// Scratch (static __device__ — no allocations allowed)
// ---------------------------------------------------------------------------
__device__ float g_hbuf[(long long)EE * TT * II];   // per-expert capacity layout, 1.07 GB
__device__ float g_shbuf[(long long)TT * ISH];      // shared-expert intermediate, 67 MB
__device__ int   g_cnt[EE];
__device__ int   g_etok[EE * TT];
__device__ float g_ewt[EE * TT];
__device__ int   g_ids[TT * TOPK];

// ---------------------------------------------------------------------------
// Helpers
// ---------------------------------------------------------------------------
__device__ __forceinline__ float tf32r(float x) {
    // round-to-nearest tf32 (unbiased; truncation would bias dot products ~1e-3)
    asm("cvt.rna.tf32.f32 %0, %1;" : "=f"(x) : "f"(x));
    return x;
}

__device__ __forceinline__ void mma_tf32(float* c, const uint32_t* a, uint32_t b0, uint32_t b1) {
    asm volatile(
        "mma.sync.aligned.m16n8k8.row.col.f32.tf32.tf32.f32 "
        "{%0,%1,%2,%3}, {%4,%5,%6,%7}, {%8,%9}, {%0,%1,%2,%3};\n"
        : "+f"(c[0]), "+f"(c[1]), "+f"(c[2]), "+f"(c[3])
        : "r"(a[0]), "r"(a[1]), "r"(a[2]), "r"(a[3]), "r"(b0), "r"(b1));
}

// ---------------------------------------------------------------------------
// Router: logits -> sigmoid -> +bias -> top-8 (desc, lower-index ties) ->
// renormalized weights * 2.5 -> scatter into per-expert lists
// ---------------------------------------------------------------------------
__global__ __launch_bounds__(256) void router_kernel(
    const float* __restrict__ X, const float* __restrict__ GW,
    const float* __restrict__ GB,
    int* __restrict__ ids, int* __restrict__ cnt,
    int* __restrict__ etok, float* __restrict__ ewt)
{
    int warp = threadIdx.x >> 5;
    int lane = threadIdx.x & 31;
    int t = blockIdx.x * 8 + warp;
    if (t >= TT) return;

    const float* xr = X + (long long)t * HH;
    float acc = 0.f;
#pragma unroll 4
    for (int h = 0; h < HH; h++)
        acc = fmaf(xr[h], GW[h * EE + lane], acc);

    float score = 1.f / (1.f + expf(-acc));
    float ch = score + GB[lane];

    int kid[TOPK];
    float kw[TOPK];
    float wsum = 0.f;
#pragma unroll
    for (int k = 0; k < TOPK; k++) {
        float bv = ch; int bi = lane;
#pragma unroll
        for (int off = 16; off > 0; off >>= 1) {
            float ov = __shfl_down_sync(0xffffffffu, bv, off);
            int   oi = __shfl_down_sync(0xffffffffu, bi, off);
            if (ov > bv || (ov == bv && oi < bi)) { bv = ov; bi = oi; }
        }
        bi = __shfl_sync(0xffffffffu, bi, 0);
        float ws = __shfl_sync(0xffffffffu, score, bi);
        if (lane == bi) ch = -1e30f;
        kid[k] = bi; kw[k] = ws; wsum += ws;
    }

    if (lane == 0) {
        float norm = 2.5f / (wsum + 1e-20f);
#pragma unroll
        for (int k = 0; k < TOPK; k++) {
            int e = kid[k];
            ids[t * TOPK + k] = e;
            int pos = atomicAdd(&cnt[e], 1);
            etok[e * TT + pos] = t;
            ewt[e * TT + pos] = kw[k] * norm;
        }
    }
}

__global__ void reset_cnt_kernel(int* cnt) {
    if (threadIdx.x < EE) cnt[threadIdx.x] = 0;
}

__global__ void ids_to_float_kernel(const int* __restrict__ ids, float* __restrict__ dst, int n) {
    int i = blockIdx.x * blockDim.x + threadIdx.x;
    if (i < n) dst[i] = (float)ids[i];
}

// ---------------------------------------------------------------------------
// Fused gate+up GEMM (tf32 MMA): C = silu(A@Bg) * (A@Bu)
// A rows gathered via idx (or identity). K fixed = 2048. Tile 128x64x32.
// Warp layout 4(M)x2(N); per-warp 32x32 via 2x4 m16n8k8 tiles.
// ---------------------------------------------------------------------------
__global__ __launch_bounds__(256, 1) void gateup_kernel(
    const float* __restrict__ X,
    const int* __restrict__ idx_base, int idx_stride,
    const int* __restrict__ cntp, int Mfixed,
    const float* __restrict__ Bg_base, const float* __restrict__ Bu_base, long long bstride,
    int N,
    float* __restrict__ C_base, long long cstride)
{
    constexpr int BM = 128, BN = 64, BK = 32, KD = HH;
    int e = blockIdx.z;
    int M = cntp ? cntp[e] : Mfixed;
    int bm0 = blockIdx.x * BM;
    if (bm0 >= M) return;
    int bn0 = blockIdx.y * BN;

    const int*   idx = idx_base ? idx_base + (long long)e * idx_stride : nullptr;
    const float* Bg  = Bg_base + (long long)e * bstride;
    const float* Bu  = Bu_base + (long long)e * bstride;
    float*       C   = C_base + (long long)e * cstride;

    __shared__ float sA[BM][BK + 4];
    __shared__ float sG[BK][BN + 4];
    __shared__ float sU[BK][BN + 4];

    const int tid = threadIdx.x;
    const int lane = tid & 31, warp = tid >> 5;
    const int g = lane >> 2, tg = lane & 3;
    const int wm = warp & 3, wn = warp >> 2;

    float accG[2][4][4];
    float accU[2][4][4];
#pragma unroll
    for (int a = 0; a < 2; a++)
#pragma unroll
        for (int b = 0; b < 4; b++)
#pragma unroll
            for (int c = 0; c < 4; c++) { accG[a][b][c] = 0.f; accU[a][b][c] = 0.f; }

    for (int k0 = 0; k0 < KD; k0 += BK) {
        // load A tile (gathered rows), convert to tf32
#pragma unroll
        for (int i = 0; i < 4; i++) {
            int li = tid + i * 256;
            int r = li >> 3, kv = li & 7;
            float4 v = make_float4(0.f, 0.f, 0.f, 0.f);
            int gm = bm0 + r;
            if (gm < M) {
                long long row = idx ? (long long)idx[gm] : (long long)gm;
                v = *reinterpret_cast<const float4*>(X + row * KD + k0 + kv * 4);
            }
            float4 tv = make_float4(tf32r(v.x), tf32r(v.y), tf32r(v.z), tf32r(v.w));
            *reinterpret_cast<float4*>(&sA[r][kv * 4]) = tv;
        }
        // load both B tiles
#pragma unroll
        for (int i = 0; i < 2; i++) {
            int li = tid + i * 256;
            int r = li >> 4, nv = li & 15;
            long long off = (long long)(k0 + r) * N + bn0 + nv * 4;
            float4 vg = *reinterpret_cast<const float4*>(Bg + off);
            float4 vu = *reinterpret_cast<const float4*>(Bu + off);
            float4 tg4 = make_float4(tf32r(vg.x), tf32r(vg.y), tf32r(vg.z), tf32r(vg.w));
            float4 tu4 = make_float4(tf32r(vu.x), tf32r(vu.y), tf32r(vu.z), tf32r(vu.w));
            *reinterpret_cast<float4*>(&sG[r][nv * 4]) = tg4;
            *reinterpret_cast<float4*>(&sU[r][nv * 4]) = tu4;
        }
        __syncthreads();

#pragma unroll
        for (int ks = 0; ks < BK / 8; ks++) {
            uint32_t a[2][4];
#pragma unroll
            for (int mi = 0; mi < 2; mi++) {
                int rb = wm * 32 + mi * 16;
                a[mi][0] = __float_as_uint(sA[rb + g][ks * 8 + tg]);
                a[mi][1] = __float_as_uint(sA[rb + g + 8][ks * 8 + tg]);
                a[mi][2] = __float_as_uint(sA[rb + g][ks * 8 + tg + 4]);
                a[mi][3] = __float_as_uint(sA[rb + g + 8][ks * 8 + tg + 4]);
            }
#pragma unroll
            for (int ni = 0; ni < 4; ni++) {
                int cb = wn * 32 + ni * 8 + g;
                uint32_t g0 = __float_as_uint(sG[ks * 8 + tg][cb]);
                uint32_t g1 = __float_as_uint(sG[ks * 8 + tg + 4][cb]);
                uint32_t u0 = __float_as_uint(sU[ks * 8 + tg][cb]);
                uint32_t u1 = __float_as_uint(sU[ks * 8 + tg + 4][cb]);
#pragma unroll
                for (int mi = 0; mi < 2; mi++) {
                    mma_tf32(accG[mi][ni], a[mi], g0, g1);
                    mma_tf32(accU[mi][ni], a[mi], u0, u1);
                }
            }
        }
        __syncthreads();
    }

    // epilogue: h = silu(g) * u
#pragma unroll
    for (int mi = 0; mi < 2; mi++) {
#pragma unroll
        for (int ni = 0; ni < 4; ni++) {
            int m0 = bm0 + wm * 32 + mi * 16 + g;
            int n0 = bn0 + wn * 32 + ni * 8 + 2 * tg;
#pragma unroll
            for (int c = 0; c < 4; c++) {
                int m = m0 + ((c >= 2) ? 8 : 0);
                int n = n0 + (c & 1);
                if (m < M) {
                    float gv = accG[mi][ni][c];
                    float uv = accU[mi][ni][c];
                    float h = gv / (1.f + expf(-gv)) * uv;
                    C[(long long)m * N + n] = h;
                }
            }
        }
    }
}

// ---------------------------------------------------------------------------
// Down-proj GEMM (tf32 MMA). Tile 128x128x32. Warp layout 2(M)x4(N),
// per-warp 64x32 via 4x4 m16n8k8 tiles.
// Routed: atomicAdd(out[tok[m]], wt[m]*c). Shared: direct store out[m].
// ---------------------------------------------------------------------------
__global__ __launch_bounds__(256, 1) void down_kernel(
    const float* __restrict__ A_base, long long astride, int K,
    const float* __restrict__ B_base, long long bstride, int N,
    const int* __restrict__ cntp, int Mfixed,
    const int* __restrict__ tok_base, const float* __restrict__ wt_base, int tw_stride,
    float* __restrict__ Out)
{
    constexpr int BM = 128, BN = 128, BK = 32;
    int e = blockIdx.z;
    int M = cntp ? cntp[e] : Mfixed;
    int bm0 = blockIdx.x * BM;
    if (bm0 >= M) return;
    int bn0 = blockIdx.y * BN;

    const float* A = A_base + (long long)e * astride;
    const float* B = B_base + (long long)e * bstride;
    const int*   tok = tok_base ? tok_base + (long long)e * tw_stride : nullptr;
    const float* wt  = wt_base  ? wt_base  + (long long)e * tw_stride : nullptr;

    __shared__ float sA[BM][BK + 4];
    __shared__ float sB[BK][BN + 4];

    const int tid = threadIdx.x;
    const int lane = tid & 31, warp = tid >> 5;
    const int g = lane >> 2, tg = lane & 3;
    const int wm = warp & 1, wn = warp >> 1;

    float acc[4][4][4];
#pragma unroll
    for (int a = 0; a < 4; a++)
#pragma unroll
        for (int b = 0; b < 4; b++)
#pragma unroll
            for (int c = 0; c < 4; c++) acc[a][b][c] = 0.f;

    for (int k0 = 0; k0 < K; k0 += BK) {
#pragma unroll
        for (int i = 0; i < 4; i++) {
            int li = tid + i * 256;
            int r = li >> 3, kv = li & 7;
            float4 v = make_float4(0.f, 0.f, 0.f, 0.f);
            int gm = bm0 + r;
            if (gm < M)
                v = *reinterpret_cast<const float4*>(A + (long long)gm * K + k0 + kv * 4);
            float4 tv = make_float4(tf32r(v.x), tf32r(v.y), tf32r(v.z), tf32r(v.w));
            *reinterpret_cast<float4*>(&sA[r][kv * 4]) = tv;
        }
#pragma unroll
        for (int i = 0; i < 4; i++) {
            int li = tid + i * 256;
            int r = li >> 5, nv = li & 31;
            long long off = (long long)(k0 + r) * N + bn0 + nv * 4;
            float4 v = *reinterpret_cast<const float4*>(B + off);
            float4 tv = make_float4(tf32r(v.x), tf32r(v.y), tf32r(v.z), tf32r(v.w));
            *reinterpret_cast<float4*>(&sB[r][nv * 4]) = tv;
        }
        __syncthreads();

#pragma unroll
        for (int ks = 0; ks < BK / 8; ks++) {
            uint32_t a[4][4];
#pragma unroll
            for (int mi = 0; mi < 4; mi++) {
                int rb = wm * 64 + mi * 16;
                a[mi][0] = __float_as_uint(sA[rb + g][ks * 8 + tg]);
                a[mi][1] = __float_as_uint(sA[rb + g + 8][ks * 8 + tg]);
                a[mi][2] = __float_as_uint(sA[rb + g][ks * 8 + tg + 4]);
                a[mi][3] = __float_as_uint(sA[rb + g + 8][ks * 8 + tg + 4]);
            }
#pragma unroll
            for (int ni = 0; ni < 4; ni++) {
                int cb = wn * 32 + ni * 8 + g;
                uint32_t b0 = __float_as_uint(sB[ks * 8 + tg][cb]);
                uint32_t b1 = __float_as_uint(sB[ks * 8 + tg + 4][cb]);
#pragma unroll
                for (int mi = 0; mi < 4; mi++)
                    mma_tf32(acc[mi][ni], a[mi], b0, b1);
            }
        }
        __syncthreads();
    }

#pragma unroll
    for (int mi = 0; mi < 4; mi++) {
#pragma unroll
        for (int ni = 0; ni < 4; ni++) {
            int m0 = bm0 + wm * 64 + mi * 16 + g;
            int n0 = bn0 + wn * 32 + ni * 8 + 2 * tg;
#pragma unroll
            for (int c = 0; c < 4; c++) {
                int m = m0 + ((c >= 2) ? 8 : 0);
                int n = n0 + (c & 1);
                if (m < M) {
                    float v = acc[mi][ni][c];
                    if (tok) {
                        int t = tok[m];
                        float w = wt[m];
                        atomicAdd(&Out[(long long)t * N + n], w * v);
                    } else {
                        Out[(long long)m * N + n] = v;
                    }
                }
            }
        }
    }
}

// ---------------------------------------------------------------------------
// Launch
// ---------------------------------------------------------------------------
extern "C" void kernel_launch(void* const* d_in, const int* in_sizes, int n_in,
                              void* d_out, int out_size)
{
    (void)in_sizes; (void)n_in;
    const float* x      = (const float*)d_in[0];
    const float* gate_w = (const float*)d_in[1];
    const float* gate_b = (const float*)d_in[2];
    const float* w_gate = (const float*)d_in[3];
    const float* w_up   = (const float*)d_in[4];
    const float* w_down = (const float*)d_in[5];
    const float* sg_w   = (const float*)d_in[6];
    const float* su_w   = (const float*)d_in[7];
    const float* sd_w   = (const float*)d_in[8];
    float* out = (float*)d_out;

    void *p_hbuf, *p_shbuf, *p_cnt, *p_etok, *p_ewt, *p_ids;
    cudaGetSymbolAddress(&p_hbuf, g_hbuf);
    cudaGetSymbolAddress(&p_shbuf, g_shbuf);
    cudaGetSymbolAddress(&p_cnt, g_cnt);
    cudaGetSymbolAddress(&p_etok, g_etok);
    cudaGetSymbolAddress(&p_ewt, g_ewt);
    cudaGetSymbolAddress(&p_ids, g_ids);

    // 1) routing
    reset_cnt_kernel<<<1, 32>>>((int*)p_cnt);
    router_kernel<<<TT / 8, 256>>>(x, gate_w, gate_b,
                                   (int*)p_ids, (int*)p_cnt,
                                   (int*)p_etok, (float*)p_ewt);

    // 2) shared expert: shbuf = silu(x@sg)*(x@su); out = shbuf @ sd (direct store)
    gateup_kernel<<<dim3(TT / 128, ISH / 64, 1), 256>>>(
        x, nullptr, 0, nullptr, TT,
        sg_w, su_w, 0, ISH, (float*)p_shbuf, 0);
    down_kernel<<<dim3(TT / 128, HH / 128, 1), 256>>>(
        (const float*)p_shbuf, 0, ISH,
        sd_w, 0, HH,
        nullptr, TT, nullptr, nullptr, 0, out);

    // 3) routed experts: hbuf = silu(xg@wg)*(xg@wu); out += wt * (hbuf @ wd)
    gateup_kernel<<<dim3(TT / 128, II / 64, EE), 256>>>(
        x, (const int*)p_etok, TT, (const int*)p_cnt, 0,
        w_gate, w_up, (long long)HH * II, II,
        (float*)p_hbuf, (long long)TT * II);
    down_kernel<<<dim3(TT / 128, HH / 128, EE), 256>>>(
        (const float*)p_hbuf, (long long)TT * II, II,
        w_down, (long long)II * HH, HH,
        (const int*)p_cnt, 0,
        (const int*)p_etok, (const float*)p_ewt, TT, out);

    // 4) topk_ids appended to output (value-cast to float), if the harness
    //    flattened the (out, topk_ids) tuple into one buffer.
    long long main_sz = (long long)TT * HH;
    if ((long long)out_size > main_sz) {
        long long tail = (long long)out_size - main_sz;
        int n = (int)((tail < (long long)TT * TOPK) ? tail : (long long)TT * TOPK);
        ids_to_float_kernel<<<(n + 255) / 256, 256>>>((const int*)p_ids, out + main_sz, n);
    }
}

// round 4
// speedup vs baseline: 1.3896x; 1.3896x over previous
#include <cuda_runtime.h>
#include <cuda_bf16.h>
#include <math.h>
#include <stdint.h>

// Problem constants
#define TT   8192
#define HH   2048
#define EE   32
#define TOPK 8
#define II   1024
#define ISH  2048   // NSH * I

// ---------------------------------------------------------------------------
// Scratch (static __device__ — no allocations allowed)
// ---------------------------------------------------------------------------
__device__ float g_hbuf[(long long)EE * TT * II];   // per-expert capacity layout
__device__ float g_shbuf[(long long)TT * ISH];      // shared-expert intermediate
__device__ int   g_cnt[EE];
__device__ int   g_etok[EE * TT];
__device__ float g_ewt[EE * TT];
__device__ int   g_ids[TT * TOPK];

// ---------------------------------------------------------------------------
// Helpers
// ---------------------------------------------------------------------------
__device__ __forceinline__ float tf32r(float x) {
    asm("cvt.rna.tf32.f32 %0, %1;" : "=f"(x) : "f"(x));
    return x;
}
__device__ __forceinline__ uint32_t f2t(float x) {
    return __float_as_uint(tf32r(x));
}

__device__ __forceinline__ void mma_tf32(float* c, const uint32_t* a, uint32_t b0, uint32_t b1) {
    asm volatile(
        "mma.sync.aligned.m16n8k8.row.col.f32.tf32.tf32.f32 "
        "{%0,%1,%2,%3}, {%4,%5,%6,%7}, {%8,%9}, {%0,%1,%2,%3};\n"
        : "+f"(c[0]), "+f"(c[1]), "+f"(c[2]), "+f"(c[3])
        : "r"(a[0]), "r"(a[1]), "r"(a[2]), "r"(a[3]), "r"(b0), "r"(b1));
}

__device__ __forceinline__ uint32_t smem_u32(const void* p) {
    return (uint32_t)__cvta_generic_to_shared(p);
}
__device__ __forceinline__ void cpa16(uint32_t dst, const void* src) {
    asm volatile("cp.async.cg.shared.global [%0], [%1], 16;\n" :: "r"(dst), "l"(src));
}
__device__ __forceinline__ void cpa_commit() {
    asm volatile("cp.async.commit_group;\n");
}
template<int N> __device__ __forceinline__ void cpa_wait() {
    asm volatile("cp.async.wait_group %0;\n" :: "n"(N));
}

// ---------------------------------------------------------------------------
// Router
// ---------------------------------------------------------------------------
__global__ __launch_bounds__(256) void router_kernel(
    const float* __restrict__ X, const float* __restrict__ GW,
    const float* __restrict__ GB,
    int* __restrict__ ids, int* __restrict__ cnt,
    int* __restrict__ etok, float* __restrict__ ewt)
{
    int warp = threadIdx.x >> 5;
    int lane = threadIdx.x & 31;
    int t = blockIdx.x * 8 + warp;
    if (t >= TT) return;

    const float* xr = X + (long long)t * HH;
    float acc = 0.f;
#pragma unroll 4
    for (int h = 0; h < HH; h++)
        acc = fmaf(xr[h], GW[h * EE + lane], acc);

    float score = 1.f / (1.f + expf(-acc));
    float ch = score + GB[lane];

    int kid[TOPK];
    float kw[TOPK];
    float wsum = 0.f;
#pragma unroll
    for (int k = 0; k < TOPK; k++) {
        float bv = ch; int bi = lane;
#pragma unroll
        for (int off = 16; off > 0; off >>= 1) {
            float ov = __shfl_down_sync(0xffffffffu, bv, off);
            int   oi = __shfl_down_sync(0xffffffffu, bi, off);
            if (ov > bv || (ov == bv && oi < bi)) { bv = ov; bi = oi; }
        }
        bi = __shfl_sync(0xffffffffu, bi, 0);
        float ws = __shfl_sync(0xffffffffu, score, bi);
        if (lane == bi) ch = -1e30f;
        kid[k] = bi; kw[k] = ws; wsum += ws;
    }

    if (lane == 0) {
        float norm = 2.5f / (wsum + 1e-20f);
#pragma unroll
        for (int k = 0; k < TOPK; k++) {
            int e = kid[k];
            ids[t * TOPK + k] = e;
            int pos = atomicAdd(&cnt[e], 1);
            etok[e * TT + pos] = t;
            ewt[e * TT + pos] = kw[k] * norm;
        }
    }
}

__global__ void reset_cnt_kernel(int* cnt) {
    if (threadIdx.x < EE) cnt[threadIdx.x] = 0;
}

__global__ void ids_to_float_kernel(const int* __restrict__ ids, float* __restrict__ dst, int n) {
    int i = blockIdx.x * blockDim.x + threadIdx.x;
    if (i < n) dst[i] = (float)ids[i];
}

// ---------------------------------------------------------------------------
// Fused gate+up GEMM, 3-stage cp.async pipeline.
// C = silu(A@Bg) * (A@Bu). Tile 128x64x32. Warps 4(M)x2(N), warp 32x32.
// ---------------------------------------------------------------------------
__global__ __launch_bounds__(256, 1) void gateup_kernel(
    const float* __restrict__ X,
    const int* __restrict__ idx_base, int idx_stride,
    const int* __restrict__ cntp, int Mfixed,
    const float* __restrict__ Bg_base, const float* __restrict__ Bu_base, long long bstride,
    int N,
    float* __restrict__ C_base, long long cstride)
{
    constexpr int BM = 128, BK = 32, KD = HH, ST = 3;
    constexpr int ALD = 36, BLD = 68;
    constexpr int ASZ = BM * ALD;       // floats per A stage
    constexpr int BSZ = BK * BLD;       // floats per G or U stage

    int e = blockIdx.z;
    int M = cntp ? cntp[e] : Mfixed;
    int bm0 = blockIdx.x * BM;
    if (bm0 >= M) return;
    int bn0 = blockIdx.y * 64;

    const int*   idx = idx_base ? idx_base + (long long)e * idx_stride : nullptr;
    const float* Bg  = Bg_base + (long long)e * bstride;
    const float* Bu  = Bu_base + (long long)e * bstride;
    float*       C   = C_base + (long long)e * cstride;

    extern __shared__ float sm[];
    float* sA = sm;                     // [ST][128][36]
    float* sG = sm + ST * ASZ;          // [ST][32][68]
    float* sU = sG + ST * BSZ;          // [ST][32][68]

    const int tid = threadIdx.x;
    const int lane = tid & 31, warp = tid >> 5;
    const int g = lane >> 2, tg = lane & 3;
    const int wm = warp & 3, wn = warp >> 2;

    // Precompute load pointers
    const float* asrc[4]; uint32_t adst[4];
#pragma unroll
    for (int i = 0; i < 4; i++) {
        int li = tid + i * 256;
        int r = li >> 3, c8 = li & 7;
        int gm = bm0 + r; if (gm > M - 1) gm = M - 1;
        long long row = idx ? (long long)idx[gm] : (long long)gm;
        asrc[i] = X + row * KD + c8 * 4;
        adst[i] = smem_u32(sA + r * ALD + c8 * 4);
    }
    const float* gsrc[2]; const float* usrc[2]; uint32_t gdst[2], udst[2];
#pragma unroll
    for (int i = 0; i < 2; i++) {
        int li = tid + i * 256;
        int r = li >> 4, c8 = li & 15;
        long long off = (long long)r * N + bn0 + c8 * 4;
        gsrc[i] = Bg + off;
        usrc[i] = Bu + off;
        gdst[i] = smem_u32(sG + r * BLD + c8 * 4);
        udst[i] = smem_u32(sU + r * BLD + c8 * 4);
    }

    auto load_stage = [&](int k, int st) {
#pragma unroll
        for (int i = 0; i < 4; i++) cpa16(adst[i] + st * ASZ * 4, asrc[i] + k * BK);
        long long boff = (long long)k * BK * N;
#pragma unroll
        for (int i = 0; i < 2; i++) {
            cpa16(gdst[i] + st * BSZ * 4, gsrc[i] + boff);
            cpa16(udst[i] + st * BSZ * 4, usrc[i] + boff);
        }
        cpa_commit();
    };

    constexpr int NK = KD / BK;
    load_stage(0, 0);
    load_stage(1, 1);

    float accG[2][4][4];
    float accU[2][4][4];
#pragma unroll
    for (int a = 0; a < 2; a++)
#pragma unroll
        for (int b = 0; b < 4; b++)
#pragma unroll
            for (int c = 0; c < 4; c++) { accG[a][b][c] = 0.f; accU[a][b][c] = 0.f; }

    for (int k = 0; k < NK; k++) {
        if (k == NK - 1) cpa_wait<0>(); else cpa_wait<1>();
        __syncthreads();
        if (k + 2 < NK) load_stage(k + 2, (k + 2) % ST);

        const float* a_s = sA + (k % ST) * ASZ;
        const float* g_s = sG + (k % ST) * BSZ;
        const float* u_s = sU + (k % ST) * BSZ;

#pragma unroll
        for (int ks = 0; ks < BK / 8; ks++) {
            uint32_t a[2][4];
#pragma unroll
            for (int mi = 0; mi < 2; mi++) {
                int rb = wm * 32 + mi * 16;
                a[mi][0] = f2t(a_s[(rb + g) * ALD + ks * 8 + tg]);
                a[mi][1] = f2t(a_s[(rb + g + 8) * ALD + ks * 8 + tg]);
                a[mi][2] = f2t(a_s[(rb + g) * ALD + ks * 8 + tg + 4]);
                a[mi][3] = f2t(a_s[(rb + g + 8) * ALD + ks * 8 + tg + 4]);
            }
#pragma unroll
            for (int ni = 0; ni < 4; ni++) {
                int cb = wn * 32 + ni * 8 + g;
                uint32_t g0 = f2t(g_s[(ks * 8 + tg) * BLD + cb]);
                uint32_t g1 = f2t(g_s[(ks * 8 + tg + 4) * BLD + cb]);
                uint32_t u0 = f2t(u_s[(ks * 8 + tg) * BLD + cb]);
                uint32_t u1 = f2t(u_s[(ks * 8 + tg + 4) * BLD + cb]);
#pragma unroll
                for (int mi = 0; mi < 2; mi++) {
                    mma_tf32(accG[mi][ni], a[mi], g0, g1);
                    mma_tf32(accU[mi][ni], a[mi], u0, u1);
                }
            }
        }
    }

    // epilogue: h = silu(g) * u
#pragma unroll
    for (int mi = 0; mi < 2; mi++) {
#pragma unroll
        for (int ni = 0; ni < 4; ni++) {
            int m0 = bm0 + wm * 32 + mi * 16 + g;
            int n0 = bn0 + wn * 32 + ni * 8 + 2 * tg;
#pragma unroll
            for (int c = 0; c < 4; c++) {
                int m = m0 + ((c >= 2) ? 8 : 0);
                int n = n0 + (c & 1);
                if (m < M) {
                    float gv = accG[mi][ni][c];
                    float uv = accU[mi][ni][c];
                    float h = gv / (1.f + expf(-gv)) * uv;
                    C[(long long)m * N + n] = h;
                }
            }
        }
    }
}

// ---------------------------------------------------------------------------
// Down-proj GEMM, 3-stage cp.async pipeline. Tile 128x128x32.
// Warps 2(M)x4(N), warp 64x32.
// Routed: atomicAdd(out[tok[m]], wt[m]*c). Shared: direct store out[m].
// ---------------------------------------------------------------------------
__global__ __launch_bounds__(256, 1) void down_kernel(
    const float* __restrict__ A_base, long long astride, int K,
    const float* __restrict__ B_base, long long bstride, int N,
    const int* __restrict__ cntp, int Mfixed,
    const int* __restrict__ tok_base, const float* __restrict__ wt_base, int tw_stride,
    float* __restrict__ Out)
{
    constexpr int BM = 128, BN = 128, BK = 32, ST = 3;
    constexpr int ALD = 36, BLD = 132;
    constexpr int ASZ = BM * ALD;
    constexpr int BSZ = BK * BLD;

    int e = blockIdx.z;
    int M = cntp ? cntp[e] : Mfixed;
    int bm0 = blockIdx.x * BM;
    if (bm0 >= M) return;
    int bn0 = blockIdx.y * BN;

    const float* A = A_base + (long long)e * astride;
    const float* B = B_base + (long long)e * bstride;
    const int*   tok = tok_base ? tok_base + (long long)e * tw_stride : nullptr;
    const float* wt  = wt_base  ? wt_base  + (long long)e * tw_stride : nullptr;

    extern __shared__ float sm[];
    float* sA = sm;                 // [ST][128][36]
    float* sB = sm + ST * ASZ;      // [ST][32][132]

    const int tid = threadIdx.x;
    const int lane = tid & 31, warp = tid >> 5;
    const int g = lane >> 2, tg = lane & 3;
    const int wm = warp & 1, wn = warp >> 1;

    const float* asrc[4]; uint32_t adst[4];
#pragma unroll
    for (int i = 0; i < 4; i++) {
        int li = tid + i * 256;
        int r = li >> 3, c8 = li & 7;
        int gm = bm0 + r;           // rows beyond M read in-capacity garbage; discarded
        asrc[i] = A + (long long)gm * K + c8 * 4;
        adst[i] = smem_u32(sA + r * ALD + c8 * 4);
    }
    const float* bsrc[4]; uint32_t bdst[4];
#pragma unroll
    for (int i = 0; i < 4; i++) {
        int li = tid + i * 256;
        int r = li >> 5, c8 = li & 31;
        bsrc[i] = B + (long long)r * N + bn0 + c8 * 4;
        bdst[i] = smem_u32(sB + r * BLD + c8 * 4);
    }

    auto load_stage = [&](int k, int st) {
#pragma unroll
        for (int i = 0; i < 4; i++) cpa16(adst[i] + st * ASZ * 4, asrc[i] + k * BK);
        long long boff = (long long)k * BK * N;
#pragma unroll
        for (int i = 0; i < 4; i++) cpa16(bdst[i] + st * BSZ * 4, bsrc[i] + boff);
        cpa_commit();
    };

    const int NK = K / BK;
    load_stage(0, 0);
    load_stage(1, 1);

    float acc[4][4][4];
#pragma unroll
    for (int a = 0; a < 4; a++)
#pragma unroll
        for (int b = 0; b < 4; b++)
#pragma unroll
            for (int c = 0; c < 4; c++) acc[a][b][c] = 0.f;

    for (int k = 0; k < NK; k++) {
        if (k == NK - 1) cpa_wait<0>(); else cpa_wait<1>();
        __syncthreads();
        if (k + 2 < NK) load_stage(k + 2, (k + 2) % ST);

        const float* a_s = sA + (k % ST) * ASZ;
        const float* b_s = sB + (k % ST) * BSZ;

#pragma unroll
        for (int ks = 0; ks < BK / 8; ks++) {
            uint32_t a[4][4];
#pragma unroll
            for (int mi = 0; mi < 4; mi++) {
                int rb = wm * 64 + mi * 16;
                a[mi][0] = f2t(a_s[(rb + g) * ALD + ks * 8 + tg]);
                a[mi][1] = f2t(a_s[(rb + g + 8) * ALD + ks * 8 + tg]);
                a[mi][2] = f2t(a_s[(rb + g) * ALD + ks * 8 + tg + 4]);
                a[mi][3] = f2t(a_s[(rb + g + 8) * ALD + ks * 8 + tg + 4]);
            }
#pragma unroll
            for (int ni = 0; ni < 4; ni++) {
                int cb = wn * 32 + ni * 8 + g;
                uint32_t b0 = f2t(b_s[(ks * 8 + tg) * BLD + cb]);
                uint32_t b1 = f2t(b_s[(ks * 8 + tg + 4) * BLD + cb]);
#pragma unroll
                for (int mi = 0; mi < 4; mi++)
                    mma_tf32(acc[mi][ni], a[mi], b0, b1);
            }
        }
    }

#pragma unroll
    for (int mi = 0; mi < 4; mi++) {
#pragma unroll
        for (int ni = 0; ni < 4; ni++) {
            int m0 = bm0 + wm * 64 + mi * 16 + g;
            int n0 = bn0 + wn * 32 + ni * 8 + 2 * tg;
#pragma unroll
            for (int c = 0; c < 4; c++) {
                int m = m0 + ((c >= 2) ? 8 : 0);
                int n = n0 + (c & 1);
                if (m < M) {
                    float v = acc[mi][ni][c];
                    if (tok) {
                        int t = tok[m];
                        float w = wt[m];
                        atomicAdd(&Out[(long long)t * N + n], w * v);
                    } else {
                        Out[(long long)m * N + n] = v;
                    }
                }
            }
        }
    }
}

// ---------------------------------------------------------------------------
// Launch
// ---------------------------------------------------------------------------
extern "C" void kernel_launch(void* const* d_in, const int* in_sizes, int n_in,
                              void* d_out, int out_size)
{
    (void)in_sizes; (void)n_in;
    const float* x      = (const float*)d_in[0];
    const float* gate_w = (const float*)d_in[1];
    const float* gate_b = (const float*)d_in[2];
    const float* w_gate = (const float*)d_in[3];
    const float* w_up   = (const float*)d_in[4];
    const float* w_down = (const float*)d_in[5];
    const float* sg_w   = (const float*)d_in[6];
    const float* su_w   = (const float*)d_in[7];
    const float* sd_w   = (const float*)d_in[8];
    float* out = (float*)d_out;

    void *p_hbuf, *p_shbuf, *p_cnt, *p_etok, *p_ewt, *p_ids;
    cudaGetSymbolAddress(&p_hbuf, g_hbuf);
    cudaGetSymbolAddress(&p_shbuf, g_shbuf);
    cudaGetSymbolAddress(&p_cnt, g_cnt);
    cudaGetSymbolAddress(&p_etok, g_etok);
    cudaGetSymbolAddress(&p_ewt, g_ewt);
    cudaGetSymbolAddress(&p_ids, g_ids);

    // smem sizes (bytes)
    const int gu_smem = 3 * (128 * 36 + 2 * 32 * 68) * 4;   // 107,520
    const int dn_smem = 3 * (128 * 36 + 32 * 132) * 4;      // 105,984
    static bool attr_done = false;
    if (!attr_done) {
        cudaFuncSetAttribute(gateup_kernel, cudaFuncAttributeMaxDynamicSharedMemorySize, gu_smem);
        cudaFuncSetAttribute(down_kernel, cudaFuncAttributeMaxDynamicSharedMemorySize, dn_smem);
        attr_done = true;
    }

    // 1) routing
    reset_cnt_kernel<<<1, 32>>>((int*)p_cnt);
    router_kernel<<<TT / 8, 256>>>(x, gate_w, gate_b,
                                   (int*)p_ids, (int*)p_cnt,
                                   (int*)p_etok, (float*)p_ewt);

    // 2) shared expert
    gateup_kernel<<<dim3(TT / 128, ISH / 64, 1), 256, gu_smem>>>(
        x, nullptr, 0, nullptr, TT,
        sg_w, su_w, 0, ISH, (float*)p_shbuf, 0);
    down_kernel<<<dim3(TT / 128, HH / 128, 1), 256, dn_smem>>>(
        (const float*)p_shbuf, 0, ISH,
        sd_w, 0, HH,
        nullptr, TT, nullptr, nullptr, 0, out);

    // 3) routed experts
    gateup_kernel<<<dim3(TT / 128, II / 64, EE), 256, gu_smem>>>(
        x, (const int*)p_etok, TT, (const int*)p_cnt, 0,
        w_gate, w_up, (long long)HH * II, II,
        (float*)p_hbuf, (long long)TT * II);
    down_kernel<<<dim3(TT / 128, HH / 128, EE), 256, dn_smem>>>(
        (const float*)p_hbuf, (long long)TT * II, II,
        w_down, (long long)II * HH, HH,
        (const int*)p_cnt, 0,
        (const int*)p_etok, (const float*)p_ewt, TT, out);

    // 4) topk_ids tail (value-cast), if present in out buffer
    long long main_sz = (long long)TT * HH;
    if ((long long)out_size > main_sz) {
        long long tail = (long long)out_size - main_sz;
        int n = (int)((tail < (long long)TT * TOPK) ? tail : (long long)TT * TOPK);
        ids_to_float_kernel<<<(n + 255) / 256, 256>>>((const int*)p_ids, out + main_sz, n);
    }
}

// round 5
// speedup vs baseline: 1.8721x; 1.3472x over previous
#include <cuda_runtime.h>
#include <cuda_bf16.h>
#include <math.h>
#include <stdint.h>

// Problem constants
#define TT   8192
#define HH   2048
#define EE   32
#define TOPK 8
#define II   1024
#define ISH  2048   // NSH * I

// ---------------------------------------------------------------------------
// Scratch (static __device__ — no allocations allowed)
// ---------------------------------------------------------------------------
__device__ float g_hbuf[(long long)EE * TT * II];   // per-expert h, tf32-rounded
__device__ float g_shbuf[(long long)TT * ISH];      // shared h, tf32-rounded
__device__ int   g_cnt[EE];
__device__ int   g_etok[EE * TT];
__device__ float g_ewt[EE * TT];
__device__ int   g_ids[TT * TOPK];

// tf32-pre-rounded operands
__device__ float g_cx[(long long)TT * HH];
__device__ float g_cwg[(long long)EE * HH * II];
__device__ float g_cwu[(long long)EE * HH * II];
__device__ float g_cwd[(long long)EE * II * HH];
__device__ float g_csg[(long long)HH * ISH];
__device__ float g_csu[(long long)HH * ISH];
__device__ float g_csd[(long long)ISH * HH];

// ---------------------------------------------------------------------------
// Helpers
// ---------------------------------------------------------------------------
__device__ __forceinline__ float tf32r(float x) {
    asm("cvt.rna.tf32.f32 %0, %1;" : "=f"(x) : "f"(x));
    return x;
}

__device__ __forceinline__ void mma_tf32(float* c, const uint32_t* a, uint32_t b0, uint32_t b1) {
    asm volatile(
        "mma.sync.aligned.m16n8k8.row.col.f32.tf32.tf32.f32 "
        "{%0,%1,%2,%3}, {%4,%5,%6,%7}, {%8,%9}, {%0,%1,%2,%3};\n"
        : "+f"(c[0]), "+f"(c[1]), "+f"(c[2]), "+f"(c[3])
        : "r"(a[0]), "r"(a[1]), "r"(a[2]), "r"(a[3]), "r"(b0), "r"(b1));
}

__device__ __forceinline__ uint32_t smem_u32(const void* p) {
    return (uint32_t)__cvta_generic_to_shared(p);
}
__device__ __forceinline__ void cpa16(uint32_t dst, const void* src) {
    asm volatile("cp.async.cg.shared.global [%0], [%1], 16;\n" :: "r"(dst), "l"(src));
}
__device__ __forceinline__ void cpa_commit() {
    asm volatile("cp.async.commit_group;\n");
}
template<int N> __device__ __forceinline__ void cpa_wait() {
    asm volatile("cp.async.wait_group %0;\n" :: "n"(N));
}

// ---------------------------------------------------------------------------
// tf32 pre-round (elementwise, float4)
// ---------------------------------------------------------------------------
__global__ __launch_bounds__(256) void conv_tf32_kernel(
    const float4* __restrict__ src, float4* __restrict__ dst, int n4)
{
    int i = blockIdx.x * blockDim.x + threadIdx.x;
    if (i < n4) {
        float4 v = src[i];
        dst[i] = make_float4(tf32r(v.x), tf32r(v.y), tf32r(v.z), tf32r(v.w));
    }
}

// ---------------------------------------------------------------------------
// Router
// ---------------------------------------------------------------------------
__global__ __launch_bounds__(256) void router_kernel(
    const float* __restrict__ X, const float* __restrict__ GW,
    const float* __restrict__ GB,
    int* __restrict__ ids, int* __restrict__ cnt,
    int* __restrict__ etok, float* __restrict__ ewt)
{
    int warp = threadIdx.x >> 5;
    int lane = threadIdx.x & 31;
    int t = blockIdx.x * 8 + warp;
    if (t >= TT) return;

    const float* xr = X + (long long)t * HH;
    float acc = 0.f;
#pragma unroll 4
    for (int h = 0; h < HH; h++)
        acc = fmaf(xr[h], GW[h * EE + lane], acc);

    float score = 1.f / (1.f + expf(-acc));
    float ch = score + GB[lane];

    int kid[TOPK];
    float kw[TOPK];
    float wsum = 0.f;
#pragma unroll
    for (int k = 0; k < TOPK; k++) {
        float bv = ch; int bi = lane;
#pragma unroll
        for (int off = 16; off > 0; off >>= 1) {
            float ov = __shfl_down_sync(0xffffffffu, bv, off);
            int   oi = __shfl_down_sync(0xffffffffu, bi, off);
            if (ov > bv || (ov == bv && oi < bi)) { bv = ov; bi = oi; }
        }
        bi = __shfl_sync(0xffffffffu, bi, 0);
        float ws = __shfl_sync(0xffffffffu, score, bi);
        if (lane == bi) ch = -1e30f;
        kid[k] = bi; kw[k] = ws; wsum += ws;
    }

    if (lane == 0) {
        float norm = 2.5f / (wsum + 1e-20f);
#pragma unroll
        for (int k = 0; k < TOPK; k++) {
            int e = kid[k];
            ids[t * TOPK + k] = e;
            int pos = atomicAdd(&cnt[e], 1);
            etok[e * TT + pos] = t;
            ewt[e * TT + pos] = kw[k] * norm;
        }
    }
}

__global__ void reset_cnt_kernel(int* cnt) {
    if (threadIdx.x < EE) cnt[threadIdx.x] = 0;
}

__global__ void ids_to_float_kernel(const int* __restrict__ ids, float* __restrict__ dst, int n) {
    int i = blockIdx.x * blockDim.x + threadIdx.x;
    if (i < n) dst[i] = (float)ids[i];
}

// ---------------------------------------------------------------------------
// Fused gate+up GEMM, 3-stage cp.async pipeline, PRE-ROUNDED tf32 operands.
// C = tf32r(silu(A@Bg) * (A@Bu)). Block tile 128x128 (per matrix), BK=32.
// Warps 2(M)x4(N); warp computes 64x32 of G and 64x32 of U.
// ---------------------------------------------------------------------------
__global__ __launch_bounds__(256, 1) void gateup_kernel(
    const float* __restrict__ X,
    const int* __restrict__ idx_base, int idx_stride,
    const int* __restrict__ cntp, int Mfixed,
    const float* __restrict__ Bg_base, const float* __restrict__ Bu_base, long long bstride,
    int N,
    float* __restrict__ C_base, long long cstride)
{
    constexpr int BM = 128, BK = 32, KD = HH, ST = 3;
    constexpr int ALD = 36;            // stride 4 mod 32 -> conflict-free A frags
    constexpr int BLD = 136;           // stride 8 mod 32 -> conflict-free B frags
    constexpr int ASZ = BM * ALD;
    constexpr int BSZ = BK * BLD;

    int e = blockIdx.z;
    int M = cntp ? cntp[e] : Mfixed;
    int bm0 = blockIdx.x * BM;
    if (bm0 >= M) return;
    int bn0 = blockIdx.y * 128;

    const int*   idx = idx_base ? idx_base + (long long)e * idx_stride : nullptr;
    const float* Bg  = Bg_base + (long long)e * bstride;
    const float* Bu  = Bu_base + (long long)e * bstride;
    float*       C   = C_base + (long long)e * cstride;

    extern __shared__ float sm[];
    float* sA = sm;                     // [ST][128][36]
    float* sG = sm + ST * ASZ;          // [ST][32][136]
    float* sU = sG + ST * BSZ;          // [ST][32][136]

    const int tid = threadIdx.x;
    const int lane = tid & 31, warp = tid >> 5;
    const int g = lane >> 2, tg = lane & 3;
    const int wm = warp & 1, wn = warp >> 1;

    // A loads: 128x32 floats = 1024 f4, 4 per thread
    const float* asrc[4]; uint32_t adst[4];
#pragma unroll
    for (int i = 0; i < 4; i++) {
        int li = tid + i * 256;
        int r = li >> 3, c8 = li & 7;
        int gm = bm0 + r; if (gm > M - 1) gm = M - 1;
        long long row = idx ? (long long)idx[gm] : (long long)gm;
        asrc[i] = X + row * KD + c8 * 4;
        adst[i] = smem_u32(sA + r * ALD + c8 * 4);
    }
    // G/U loads: 32x128 floats = 1024 f4 each, 4 per thread
    const float* gsrc[4]; const float* usrc[4]; uint32_t gdst[4], udst[4];
#pragma unroll
    for (int i = 0; i < 4; i++) {
        int li = tid + i * 256;
        int r = li >> 5, c4 = li & 31;
        long long off = (long long)r * N + bn0 + c4 * 4;
        gsrc[i] = Bg + off;
        usrc[i] = Bu + off;
        gdst[i] = smem_u32(sG + r * BLD + c4 * 4);
        udst[i] = smem_u32(sU + r * BLD + c4 * 4);
    }

    auto load_stage = [&](int k, int st) {
#pragma unroll
        for (int i = 0; i < 4; i++) cpa16(adst[i] + st * ASZ * 4, asrc[i] + k * BK);
        long long boff = (long long)k * BK * N;
#pragma unroll
        for (int i = 0; i < 4; i++) {
            cpa16(gdst[i] + st * BSZ * 4, gsrc[i] + boff);
            cpa16(udst[i] + st * BSZ * 4, usrc[i] + boff);
        }
        cpa_commit();
    };

    constexpr int NK = KD / BK;
    load_stage(0, 0);
    load_stage(1, 1);

    float accG[4][4][4];
    float accU[4][4][4];
#pragma unroll
    for (int a = 0; a < 4; a++)
#pragma unroll
        for (int b = 0; b < 4; b++)
#pragma unroll
            for (int c = 0; c < 4; c++) { accG[a][b][c] = 0.f; accU[a][b][c] = 0.f; }

    for (int k = 0; k < NK; k++) {
        if (k == NK - 1) cpa_wait<0>(); else cpa_wait<1>();
        __syncthreads();
        if (k + 2 < NK) load_stage(k + 2, (k + 2) % ST);

        const float* a_s = sA + (k % ST) * ASZ;
        const float* g_s = sG + (k % ST) * BSZ;
        const float* u_s = sU + (k % ST) * BSZ;

#pragma unroll
        for (int ks = 0; ks < BK / 8; ks++) {
            uint32_t a[4][4];
#pragma unroll
            for (int mi = 0; mi < 4; mi++) {
                int rb = wm * 64 + mi * 16;
                a[mi][0] = __float_as_uint(a_s[(rb + g) * ALD + ks * 8 + tg]);
                a[mi][1] = __float_as_uint(a_s[(rb + g + 8) * ALD + ks * 8 + tg]);
                a[mi][2] = __float_as_uint(a_s[(rb + g) * ALD + ks * 8 + tg + 4]);
                a[mi][3] = __float_as_uint(a_s[(rb + g + 8) * ALD + ks * 8 + tg + 4]);
            }
#pragma unroll
            for (int ni = 0; ni < 4; ni++) {
                int cb = wn * 32 + ni * 8 + g;
                uint32_t g0 = __float_as_uint(g_s[(ks * 8 + tg) * BLD + cb]);
                uint32_t g1 = __float_as_uint(g_s[(ks * 8 + tg + 4) * BLD + cb]);
                uint32_t u0 = __float_as_uint(u_s[(ks * 8 + tg) * BLD + cb]);
                uint32_t u1 = __float_as_uint(u_s[(ks * 8 + tg + 4) * BLD + cb]);
#pragma unroll
                for (int mi = 0; mi < 4; mi++) {
                    mma_tf32(accG[mi][ni], a[mi], g0, g1);
                    mma_tf32(accU[mi][ni], a[mi], u0, u1);
                }
            }
        }
    }

    // epilogue: h = tf32r(silu(g) * u)  (pre-rounded for the down GEMM)
#pragma unroll
    for (int mi = 0; mi < 4; mi++) {
#pragma unroll
        for (int ni = 0; ni < 4; ni++) {
            int m0 = bm0 + wm * 64 + mi * 16 + g;
            int n0 = bn0 + wn * 32 + ni * 8 + 2 * tg;
#pragma unroll
            for (int c = 0; c < 4; c++) {
                int m = m0 + ((c >= 2) ? 8 : 0);
                int n = n0 + (c & 1);
                if (m < M) {
                    float gv = accG[mi][ni][c];
                    float uv = accU[mi][ni][c];
                    float h = gv / (1.f + expf(-gv)) * uv;
                    C[(long long)m * N + n] = tf32r(h);
                }
            }
        }
    }
}

// ---------------------------------------------------------------------------
// Down-proj GEMM, 3-stage cp.async, PRE-ROUNDED tf32 operands.
// Block tile 128x256, BK=32. Warps 2(M)x4(N); warp 64x64.
// Routed: atomicAdd(out[tok[m]], wt[m]*c). Shared: direct store out[m].
// ---------------------------------------------------------------------------
__global__ __launch_bounds__(256, 1) void down_kernel(
    const float* __restrict__ A_base, long long astride, int K,
    const float* __restrict__ B_base, long long bstride, int N,
    const int* __restrict__ cntp, int Mfixed,
    const int* __restrict__ tok_base, const float* __restrict__ wt_base, int tw_stride,
    float* __restrict__ Out)
{
    constexpr int BM = 128, BN = 256, BK = 32, ST = 3;
    constexpr int ALD = 36;
    constexpr int BLD = 264;           // stride 8 mod 32 -> conflict-free
    constexpr int ASZ = BM * ALD;
    constexpr int BSZ = BK * BLD;

    int e = blockIdx.z;
    int M = cntp ? cntp[e] : Mfixed;
    int bm0 = blockIdx.x * BM;
    if (bm0 >= M) return;
    int bn0 = blockIdx.y * BN;

    const float* A = A_base + (long long)e * astride;
    const float* B = B_base + (long long)e * bstride;
    const int*   tok = tok_base ? tok_base + (long long)e * tw_stride : nullptr;
    const float* wt  = wt_base  ? wt_base  + (long long)e * tw_stride : nullptr;

    extern __shared__ float sm[];
    float* sA = sm;                 // [ST][128][36]
    float* sB = sm + ST * ASZ;      // [ST][32][264]

    const int tid = threadIdx.x;
    const int lane = tid & 31, warp = tid >> 5;
    const int g = lane >> 2, tg = lane & 3;
    const int wm = warp & 1, wn = warp >> 1;

    const float* asrc[4]; uint32_t adst[4];
#pragma unroll
    for (int i = 0; i < 4; i++) {
        int li = tid + i * 256;
        int r = li >> 3, c8 = li & 7;
        int gm = bm0 + r;           // rows beyond M read in-capacity data; discarded
        asrc[i] = A + (long long)gm * K + c8 * 4;
        adst[i] = smem_u32(sA + r * ALD + c8 * 4);
    }
    // B loads: 32x256 floats = 2048 f4, 8 per thread
    const float* bsrc[8]; uint32_t bdst[8];
#pragma unroll
    for (int i = 0; i < 8; i++) {
        int li = tid + i * 256;
        int r = li >> 6, c4 = li & 63;
        bsrc[i] = B + (long long)r * N + bn0 + c4 * 4;
        bdst[i] = smem_u32(sB + r * BLD + c4 * 4);
    }

    auto load_stage = [&](int k, int st) {
#pragma unroll
        for (int i = 0; i < 4; i++) cpa16(adst[i] + st * ASZ * 4, asrc[i] + k * BK);
        long long boff = (long long)k * BK * N;
#pragma unroll
        for (int i = 0; i < 8; i++) cpa16(bdst[i] + st * BSZ * 4, bsrc[i] + boff);
        cpa_commit();
    };

    const int NK = K / BK;
    load_stage(0, 0);
    load_stage(1, 1);

    float acc[4][8][4];
#pragma unroll
    for (int a = 0; a < 4; a++)
#pragma unroll
        for (int b = 0; b < 8; b++)
#pragma unroll
            for (int c = 0; c < 4; c++) acc[a][b][c] = 0.f;

    for (int k = 0; k < NK; k++) {
        if (k == NK - 1) cpa_wait<0>(); else cpa_wait<1>();
        __syncthreads();
        if (k + 2 < NK) load_stage(k + 2, (k + 2) % ST);

        const float* a_s = sA + (k % ST) * ASZ;
        const float* b_s = sB + (k % ST) * BSZ;

#pragma unroll
        for (int ks = 0; ks < BK / 8; ks++) {
            uint32_t a[4][4];
#pragma unroll
            for (int mi = 0; mi < 4; mi++) {
                int rb = wm * 64 + mi * 16;
                a[mi][0] = __float_as_uint(a_s[(rb + g) * ALD + ks * 8 + tg]);
                a[mi][1] = __float_as_uint(a_s[(rb + g + 8) * ALD + ks * 8 + tg]);
                a[mi][2] = __float_as_uint(a_s[(rb + g) * ALD + ks * 8 + tg + 4]);
                a[mi][3] = __float_as_uint(a_s[(rb + g + 8) * ALD + ks * 8 + tg + 4]);
            }
#pragma unroll
            for (int ni = 0; ni < 8; ni++) {
                int cb = wn * 64 + ni * 8 + g;
                uint32_t b0 = __float_as_uint(b_s[(ks * 8 + tg) * BLD + cb]);
                uint32_t b1 = __float_as_uint(b_s[(ks * 8 + tg + 4) * BLD + cb]);
#pragma unroll
                for (int mi = 0; mi < 4; mi++)
                    mma_tf32(acc[mi][ni], a[mi], b0, b1);
            }
        }
    }

#pragma unroll
    for (int mi = 0; mi < 4; mi++) {
#pragma unroll
        for (int ni = 0; ni < 8; ni++) {
            int m0 = bm0 + wm * 64 + mi * 16 + g;
            int n0 = bn0 + wn * 64 + ni * 8 + 2 * tg;
#pragma unroll
            for (int c = 0; c < 4; c++) {
                int m = m0 + ((c >= 2) ? 8 : 0);
                int n = n0 + (c & 1);
                if (m < M) {
                    float v = acc[mi][ni][c];
                    if (tok) {
                        int t = tok[m];
                        float w = wt[m];
                        atomicAdd(&Out[(long long)t * N + n], w * v);
                    } else {
                        Out[(long long)m * N + n] = v;
                    }
                }
            }
        }
    }
}

// ---------------------------------------------------------------------------
// Launch
// ---------------------------------------------------------------------------
extern "C" void kernel_launch(void* const* d_in, const int* in_sizes, int n_in,
                              void* d_out, int out_size)
{
    (void)in_sizes; (void)n_in;
    const float* x      = (const float*)d_in[0];
    const float* gate_w = (const float*)d_in[1];
    const float* gate_b = (const float*)d_in[2];
    const float* w_gate = (const float*)d_in[3];
    const float* w_up   = (const float*)d_in[4];
    const float* w_down = (const float*)d_in[5];
    const float* sg_w   = (const float*)d_in[6];
    const float* su_w   = (const float*)d_in[7];
    const float* sd_w   = (const float*)d_in[8];
    float* out = (float*)d_out;

    void *p_hbuf, *p_shbuf, *p_cnt, *p_etok, *p_ewt, *p_ids;
    void *p_cx, *p_cwg, *p_cwu, *p_cwd, *p_csg, *p_csu, *p_csd;
    cudaGetSymbolAddress(&p_hbuf, g_hbuf);
    cudaGetSymbolAddress(&p_shbuf, g_shbuf);
    cudaGetSymbolAddress(&p_cnt, g_cnt);
    cudaGetSymbolAddress(&p_etok, g_etok);
    cudaGetSymbolAddress(&p_ewt, g_ewt);
    cudaGetSymbolAddress(&p_ids, g_ids);
    cudaGetSymbolAddress(&p_cx, g_cx);
    cudaGetSymbolAddress(&p_cwg, g_cwg);
    cudaGetSymbolAddress(&p_cwu, g_cwu);
    cudaGetSymbolAddress(&p_cwd, g_cwd);
    cudaGetSymbolAddress(&p_csg, g_csg);
    cudaGetSymbolAddress(&p_csu, g_csu);
    cudaGetSymbolAddress(&p_csd, g_csd);

    const int gu_smem = 3 * (128 * 36 + 2 * 32 * 136) * 4;  // 159,744
    const int dn_smem = 3 * (128 * 36 + 32 * 264) * 4;      // 156,672
    static bool attr_done = false;
    if (!attr_done) {
        cudaFuncSetAttribute(gateup_kernel, cudaFuncAttributeMaxDynamicSharedMemorySize, gu_smem);
        cudaFuncSetAttribute(down_kernel, cudaFuncAttributeMaxDynamicSharedMemorySize, dn_smem);
        attr_done = true;
    }

    // 0) pre-round all GEMM operands to tf32 (rna) — removes cvt from hot loops
    auto conv = [](const float* s, void* d, long long n) {
        int n4 = (int)(n >> 2);
        conv_tf32_kernel<<<(n4 + 255) / 256, 256>>>((const float4*)s, (float4*)d, n4);
    };
    conv(x,      p_cx,  (long long)TT * HH);
    conv(w_gate, p_cwg, (long long)EE * HH * II);
    conv(w_up,   p_cwu, (long long)EE * HH * II);
    conv(w_down, p_cwd, (long long)EE * II * HH);
    conv(sg_w,   p_csg, (long long)HH * ISH);
    conv(su_w,   p_csu, (long long)HH * ISH);
    conv(sd_w,   p_csd, (long long)ISH * HH);

    // 1) routing (raw fp32 x)
    reset_cnt_kernel<<<1, 32>>>((int*)p_cnt);
    router_kernel<<<TT / 8, 256>>>(x, gate_w, gate_b,
                                   (int*)p_ids, (int*)p_cnt,
                                   (int*)p_etok, (float*)p_ewt);

    // 2) shared expert
    gateup_kernel<<<dim3(TT / 128, ISH / 128, 1), 256, gu_smem>>>(
        (const float*)p_cx, nullptr, 0, nullptr, TT,
        (const float*)p_csg, (const float*)p_csu, 0, ISH, (float*)p_shbuf, 0);
    down_kernel<<<dim3(TT / 128, HH / 256, 1), 256, dn_smem>>>(
        (const float*)p_shbuf, 0, ISH,
        (const float*)p_csd, 0, HH,
        nullptr, TT, nullptr, nullptr, 0, out);

    // 3) routed experts
    gateup_kernel<<<dim3(TT / 128, II / 128, EE), 256, gu_smem>>>(
        (const float*)p_cx, (const int*)p_etok, TT, (const int*)p_cnt, 0,
        (const float*)p_cwg, (const float*)p_cwu, (long long)HH * II, II,
        (float*)p_hbuf, (long long)TT * II);
    down_kernel<<<dim3(TT / 128, HH / 256, EE), 256, dn_smem>>>(
        (const float*)p_hbuf, (long long)TT * II, II,
        (const float*)p_cwd, (long long)II * HH, HH,
        (const int*)p_cnt, 0,
        (const int*)p_etok, (const float*)p_ewt, TT, out);

    // 4) topk_ids tail (value-cast), if present in out buffer
    long long main_sz = (long long)TT * HH;
    if ((long long)out_size > main_sz) {
        long long tail = (long long)out_size - main_sz;
        int n = (int)((tail < (long long)TT * TOPK) ? tail : (long long)TT * TOPK);
        ids_to_float_kernel<<<(n + 255) / 256, 256>>>((const int*)p_ids, out + main_sz, n);
    }
}

// round 10
// speedup vs baseline: 2.0644x; 1.1027x over previous
#include <cuda_runtime.h>
#include <cuda_fp16.h>
#include <math.h>
#include <stdint.h>

// Problem constants
#define TT   8192
#define HH   2048
#define EE   32
#define TOPK 8
#define II   1024
#define ISH  2048   // NSH * I

// ---------------------------------------------------------------------------
// Scratch (static __device__ — no allocations allowed)
// ---------------------------------------------------------------------------
__device__ __half g_hbuf[(long long)EE * TT * II];   // per-expert h (fp16)
__device__ __half g_shbuf[(long long)TT * ISH];      // shared h (fp16)
__device__ int    g_cnt[EE];
__device__ int    g_etok[EE * TT];
__device__ float  g_ewt[EE * TT];
__device__ int    g_ids[TT * TOPK];

// fp16 operands; weights TRANSPOSED to [N][K] K-major
__device__ __half g_cx[(long long)TT * HH];
__device__ __half g_wgT[(long long)EE * II * HH];    // [e][I][H]
__device__ __half g_wuT[(long long)EE * II * HH];    // [e][I][H]
__device__ __half g_wdT[(long long)EE * HH * II];    // [e][H][I]
__device__ __half g_sgT[(long long)ISH * HH];
__device__ __half g_suT[(long long)ISH * HH];
__device__ __half g_sdT[(long long)HH * ISH];

// ---------------------------------------------------------------------------
// Helpers
// ---------------------------------------------------------------------------
__device__ __forceinline__ uint32_t smem_u32(const void* p) {
    return (uint32_t)__cvta_generic_to_shared(p);
}
__device__ __forceinline__ void cpa16(uint32_t dst, const void* src) {
    asm volatile("cp.async.cg.shared.global [%0], [%1], 16;\n" :: "r"(dst), "l"(src));
}
__device__ __forceinline__ void cpa_commit() {
    asm volatile("cp.async.commit_group;\n");
}
template<int N> __device__ __forceinline__ void cpa_wait() {
    asm volatile("cp.async.wait_group %0;\n" :: "n"(N));
}

// m16n8k16 fp16 MMA, fp32 accumulate
__device__ __forceinline__ void mma_fp16(float* c, const uint32_t* a, uint32_t b0, uint32_t b1) {
    asm volatile(
        "mma.sync.aligned.m16n8k16.row.col.f32.f16.f16.f32 "
        "{%0,%1,%2,%3}, {%4,%5,%6,%7}, {%8,%9}, {%0,%1,%2,%3};\n"
        : "+f"(c[0]), "+f"(c[1]), "+f"(c[2]), "+f"(c[3])
        : "r"(a[0]), "r"(a[1]), "r"(a[2]), "r"(a[3]), "r"(b0), "r"(b1));
}

// smem layout: rows of 64 halves (128B) split into 8 x 16B chunks,
// physical chunk = logical chunk ^ (row & 7). Conflict-free for cp.async
// stores (consecutive rows per 8 lanes) and fragment LDS.32 reads (proven
// by bank arithmetic: bank = ((chunk^g)*4 + tg) mod 32 covers all 32).
__device__ __forceinline__ uint32_t tile_off(int row, int chunk16) {
    return (uint32_t)(row * 128 + ((chunk16 ^ (row & 7)) << 4));
}

// ---------------------------------------------------------------------------
// Prep kernels
// ---------------------------------------------------------------------------
__global__ __launch_bounds__(256) void conv_half_kernel(
    const float4* __restrict__ src, __half2* __restrict__ dst, int n4)
{
    int i = blockIdx.x * blockDim.x + threadIdx.x;
    if (i < n4) {
        float4 v = src[i];
        dst[i * 2 + 0] = __floats2half2_rn(v.x, v.y);
        dst[i * 2 + 1] = __floats2half2_rn(v.z, v.w);
    }
}

// [K][N] fp32 -> [N][K] fp16 transpose
__global__ __launch_bounds__(256) void trans_half_kernel(
    const float* __restrict__ src, __half* __restrict__ dst, int K, int N)
{
    __shared__ float tb[32][33];
    long long base = (long long)blockIdx.z * K * (long long)N;
    long long obase = (long long)blockIdx.z * K * (long long)N;
    int n0 = blockIdx.x * 32, k0 = blockIdx.y * 32;
    int tx = threadIdx.x, ty = threadIdx.y;
#pragma unroll
    for (int i = 0; i < 4; i++) {
        int kk = k0 + ty + i * 8;
        tb[ty + i * 8][tx] = src[base + (long long)kk * N + n0 + tx];
    }
    __syncthreads();
#pragma unroll
    for (int i = 0; i < 4; i++) {
        int nn = n0 + ty + i * 8;
        if (tx < 16) {
            __half2 v = __floats2half2_rn(tb[2 * tx][ty + i * 8], tb[2 * tx + 1][ty + i * 8]);
            *reinterpret_cast<__half2*>(&dst[obase + (long long)nn * K + k0 + 2 * tx]) = v;
        }
    }
}

// ---------------------------------------------------------------------------
// Router (fp32, unchanged semantics)
// ---------------------------------------------------------------------------
__global__ __launch_bounds__(256) void router_kernel(
    const float* __restrict__ X, const float* __restrict__ GW,
    const float* __restrict__ GB,
    int* __restrict__ ids, int* __restrict__ cnt,
    int* __restrict__ etok, float* __restrict__ ewt)
{
    int warp = threadIdx.x >> 5;
    int lane = threadIdx.x & 31;
    int t = blockIdx.x * 8 + warp;
    if (t >= TT) return;

    const float* xr = X + (long long)t * HH;
    float acc = 0.f;
#pragma unroll 4
    for (int h = 0; h < HH; h++)
        acc = fmaf(xr[h], GW[h * EE + lane], acc);

    float score = 1.f / (1.f + expf(-acc));
    float ch = score + GB[lane];

    int kid[TOPK];
    float kw[TOPK];
    float wsum = 0.f;
#pragma unroll
    for (int k = 0; k < TOPK; k++) {
        float bv = ch; int bi = lane;
#pragma unroll
        for (int off = 16; off > 0; off >>= 1) {
            float ov = __shfl_down_sync(0xffffffffu, bv, off);
            int   oi = __shfl_down_sync(0xffffffffu, bi, off);
            if (ov > bv || (ov == bv && oi < bi)) { bv = ov; bi = oi; }
        }
        bi = __shfl_sync(0xffffffffu, bi, 0);
        float ws = __shfl_sync(0xffffffffu, score, bi);
        if (lane == bi) ch = -1e30f;
        kid[k] = bi; kw[k] = ws; wsum += ws;
    }

    if (lane == 0) {
        float norm = 2.5f / (wsum + 1e-20f);
#pragma unroll
        for (int k = 0; k < TOPK; k++) {
            int e = kid[k];
            ids[t * TOPK + k] = e;
            int pos = atomicAdd(&cnt[e], 1);
            etok[e * TT + pos] = t;
            ewt[e * TT + pos] = kw[k] * norm;
        }
    }
}

__global__ void reset_cnt_kernel(int* cnt) {
    if (threadIdx.x < EE) cnt[threadIdx.x] = 0;
}
__global__ void ids_to_float_kernel(const int* __restrict__ ids, float* __restrict__ dst, int n) {
    int i = blockIdx.x * blockDim.x + threadIdx.x;
    if (i < n) dst[i] = (float)ids[i];
}

// ---------------------------------------------------------------------------
// Fused gate+up GEMM (fp16 HMMA): C = fp16(silu(A@BgT^T) * (A@BuT^T))
// Block 128x64 (G and U), BK=64, ST=3 (32KB/stage -> 2 CTAs/SM).
// Warps 4(M)x2(N); warp: 32x32 of G and 32x32 of U.
// ---------------------------------------------------------------------------
__global__ __launch_bounds__(256, 2) void gateup_kernel(
    const __half* __restrict__ X,
    const int* __restrict__ idx_base, int idx_stride,
    const int* __restrict__ cntp, int Mfixed,
    const __half* __restrict__ BgT_base, const __half* __restrict__ BuT_base, long long bstride,
    int N, __half* __restrict__ C_base, long long cstride)
{
    constexpr int KD = HH, BK = 64, NK = KD / BK, ST = 3;
    constexpr int ABYTES = 128 * 128;   // 128 rows x 128B
    constexpr int BBYTES = 64 * 128;    // 64 rows x 128B

    int e = blockIdx.z;
    int M = cntp ? cntp[e] : Mfixed;
    int bm0 = blockIdx.x * 128;
    if (bm0 >= M) return;
    int bn0 = blockIdx.y * 64;

    const int*    idx = idx_base ? idx_base + (long long)e * idx_stride : nullptr;
    const __half* BgT = BgT_base + (long long)e * bstride;
    const __half* BuT = BuT_base + (long long)e * bstride;
    __half*       C   = C_base + (long long)e * cstride;

    extern __shared__ char smem[];
    uint32_t sA = smem_u32(smem);                        // ST x 16KB
    uint32_t sG = sA + ST * ABYTES;                      // ST x 8KB
    uint32_t sU = sG + ST * BBYTES;                      // ST x 8KB

    const int tid = threadIdx.x;
    const int lane = tid & 31, warp = tid >> 5;
    const int g = lane >> 2, tg = lane & 3;
    const int wm = warp & 3, wn = warp >> 2;

    // cp.async mappings: A 1024 granules (4/thr), G/U 512 (2/thr)
    const __half* asrc[4]; uint32_t adst[4];
#pragma unroll
    for (int i = 0; i < 4; i++) {
        int li = tid + i * 256; int r = li & 127, c = li >> 7;
        int gm = bm0 + r; if (gm > M - 1) gm = M - 1;
        long long row = idx ? (long long)idx[gm] : (long long)gm;
        asrc[i] = X + row * KD + c * 8;
        adst[i] = sA + tile_off(r, c);
    }
    const __half* gsrc[2]; const __half* usrc[2]; uint32_t gdst[2], udst[2];
#pragma unroll
    for (int i = 0; i < 2; i++) {
        int li = tid + i * 256; int r = li & 63, c = li >> 6;
        gsrc[i] = BgT + (long long)(bn0 + r) * KD + c * 8;
        usrc[i] = BuT + (long long)(bn0 + r) * KD + c * 8;
        gdst[i] = sG + tile_off(r, c);
        udst[i] = sU + tile_off(r, c);
    }

    auto load_stage = [&](int t, int s) {
        int kf = t * BK;
#pragma unroll
        for (int i = 0; i < 4; i++) cpa16(adst[i] + s * ABYTES, asrc[i] + kf);
#pragma unroll
        for (int i = 0; i < 2; i++) {
            cpa16(gdst[i] + s * BBYTES, gsrc[i] + kf);
            cpa16(udst[i] + s * BBYTES, usrc[i] + kf);
        }
        cpa_commit();
    };

    load_stage(0, 0);
    load_stage(1, 1);

    float accG[2][4][4], accU[2][4][4];
#pragma unroll
    for (int a = 0; a < 2; a++)
#pragma unroll
        for (int b = 0; b < 4; b++)
#pragma unroll
            for (int c = 0; c < 4; c++) { accG[a][b][c] = 0.f; accU[a][b][c] = 0.f; }

    const __half* smh = (const __half*)smem;

    for (int k = 0; k < NK; k++) {
        if (k == NK - 1) cpa_wait<0>(); else cpa_wait<1>();
        __syncthreads();
        if (k + 2 < NK) load_stage(k + 2, (k + 2) % ST);

        const __half* a_s = smh + (k % ST) * (ABYTES / 2);
        const __half* g_s = smh + (ST * ABYTES + (k % ST) * BBYTES) / 2;
        const __half* u_s = smh + (ST * ABYTES + ST * BBYTES + (k % ST) * BBYTES) / 2;

#pragma unroll
        for (int ks = 0; ks < BK / 16; ks++) {
            uint32_t a[2][4];
#pragma unroll
            for (int mi = 0; mi < 2; mi++) {
                int r0 = wm * 32 + mi * 16 + g, r1 = r0 + 8;
                a[mi][0] = *(const uint32_t*)(a_s + r0 * 64 + (((2 * ks) ^ (r0 & 7)) << 3) + tg * 2);
                a[mi][1] = *(const uint32_t*)(a_s + r1 * 64 + (((2 * ks) ^ (r1 & 7)) << 3) + tg * 2);
                a[mi][2] = *(const uint32_t*)(a_s + r0 * 64 + (((2 * ks + 1) ^ (r0 & 7)) << 3) + tg * 2);
                a[mi][3] = *(const uint32_t*)(a_s + r1 * 64 + (((2 * ks + 1) ^ (r1 & 7)) << 3) + tg * 2);
            }
#pragma unroll
            for (int ni = 0; ni < 4; ni++) {
                int rb = wn * 32 + ni * 8 + g;
                uint32_t g0 = *(const uint32_t*)(g_s + rb * 64 + (((2 * ks) ^ (rb & 7)) << 3) + tg * 2);
                uint32_t g1 = *(const uint32_t*)(g_s + rb * 64 + (((2 * ks + 1) ^ (rb & 7)) << 3) + tg * 2);
                uint32_t u0 = *(const uint32_t*)(u_s + rb * 64 + (((2 * ks) ^ (rb & 7)) << 3) + tg * 2);
                uint32_t u1 = *(const uint32_t*)(u_s + rb * 64 + (((2 * ks + 1) ^ (rb & 7)) << 3) + tg * 2);
#pragma unroll
                for (int mi = 0; mi < 2; mi++) {
                    mma_fp16(accG[mi][ni], a[mi], g0, g1);
                    mma_fp16(accU[mi][ni], a[mi], u0, u1);
                }
            }
        }
    }

    // epilogue: h = fp16(silu(g)*u), half2 stores
#pragma unroll
    for (int mi = 0; mi < 2; mi++) {
#pragma unroll
        for (int ni = 0; ni < 4; ni++) {
            int m0 = bm0 + wm * 32 + mi * 16 + g;
            int n0 = bn0 + wn * 32 + ni * 8 + 2 * tg;
#pragma unroll
            for (int half = 0; half < 2; half++) {
                int m = m0 + half * 8;
                if (m < M) {
                    float gv0 = accG[mi][ni][half * 2 + 0], uv0 = accU[mi][ni][half * 2 + 0];
                    float gv1 = accG[mi][ni][half * 2 + 1], uv1 = accU[mi][ni][half * 2 + 1];
                    float h0 = gv0 / (1.f + expf(-gv0)) * uv0;
                    float h1 = gv1 / (1.f + expf(-gv1)) * uv1;
                    *reinterpret_cast<__half2*>(&C[(long long)m * N + n0]) = __floats2half2_rn(h0, h1);
                }
            }
        }
    }
}

// ---------------------------------------------------------------------------
// Down-proj GEMM (fp16 HMMA). Block 128x128, BK=64, ST=3 (32KB/stage).
// Warps 2(M)x4(N); warp 64x32.
// Routed: atomicAdd(out[tok[m]], wt[m]*d). Shared: float2 direct store.
// ---------------------------------------------------------------------------
__global__ __launch_bounds__(256, 2) void down_kernel(
    const __half* __restrict__ A_base, long long astride, int K,
    const __half* __restrict__ BT_base, long long bstride, int N,
    const int* __restrict__ cntp, int Mfixed,
    const int* __restrict__ tok_base, const float* __restrict__ wt_base, int tw_stride,
    float* __restrict__ Out)
{
    constexpr int BK = 64, ST = 3;
    constexpr int ABYTES = 128 * 128;
    constexpr int BBYTES = 128 * 128;

    int e = blockIdx.z;
    int M = cntp ? cntp[e] : Mfixed;
    int bm0 = blockIdx.x * 128;
    if (bm0 >= M) return;
    int bn0 = blockIdx.y * 128;
    const int NK = K / BK;

    const __half* A  = A_base + (long long)e * astride;
    const __half* BT = BT_base + (long long)e * bstride;
    const int*    tok = tok_base ? tok_base + (long long)e * tw_stride : nullptr;
    const float*  wt  = wt_base  ? wt_base  + (long long)e * tw_stride : nullptr;

    extern __shared__ char smem[];
    uint32_t sA = smem_u32(smem);
    uint32_t sB = sA + ST * ABYTES;

    const int tid = threadIdx.x;
    const int lane = tid & 31, warp = tid >> 5;
    const int g = lane >> 2, tg = lane & 3;
    const int wm = warp & 1, wn = warp >> 1;

    const __half* asrc[4]; uint32_t adst[4];
    const __half* bsrc[4]; uint32_t bdst[4];
#pragma unroll
    for (int i = 0; i < 4; i++) {
        int li = tid + i * 256; int r = li & 127, c = li >> 7;
        int gm = bm0 + r;                           // within expert capacity
        asrc[i] = A + (long long)gm * K + c * 8;
        adst[i] = sA + tile_off(r, c);
        bsrc[i] = BT + (long long)(bn0 + r) * K + c * 8;
        bdst[i] = sB + tile_off(r, c);
    }

    auto load_stage = [&](int t, int s) {
        int kf = t * BK;
#pragma unroll
        for (int i = 0; i < 4; i++) {
            cpa16(adst[i] + s * ABYTES, asrc[i] + kf);
            cpa16(bdst[i] + s * BBYTES, bsrc[i] + kf);
        }
        cpa_commit();
    };

    load_stage(0, 0);
    load_stage(1, 1);

    float acc[4][4][4];
#pragma unroll
    for (int a = 0; a < 4; a++)
#pragma unroll
        for (int b = 0; b < 4; b++)
#pragma unroll
            for (int c = 0; c < 4; c++) acc[a][b][c] = 0.f;

    const __half* smh = (const __half*)smem;

    for (int k = 0; k < NK; k++) {
        if (k == NK - 1) cpa_wait<0>(); else cpa_wait<1>();
        __syncthreads();
        if (k + 2 < NK) load_stage(k + 2, (k + 2) % ST);

        const __half* a_s = smh + (k % ST) * (ABYTES / 2);
        const __half* b_s = smh + (ST * ABYTES + (k % ST) * BBYTES) / 2;

#pragma unroll
        for (int ks = 0; ks < BK / 16; ks++) {
            uint32_t a[4][4];
#pragma unroll
            for (int mi = 0; mi < 4; mi++) {
                int r0 = wm * 64 + mi * 16 + g, r1 = r0 + 8;
                a[mi][0] = *(const uint32_t*)(a_s + r0 * 64 + (((2 * ks) ^ (r0 & 7)) << 3) + tg * 2);
                a[mi][1] = *(const uint32_t*)(a_s + r1 * 64 + (((2 * ks) ^ (r1 & 7)) << 3) + tg * 2);
                a[mi][2] = *(const uint32_t*)(a_s + r0 * 64 + (((2 * ks + 1) ^ (r0 & 7)) << 3) + tg * 2);
                a[mi][3] = *(const uint32_t*)(a_s + r1 * 64 + (((2 * ks + 1) ^ (r1 & 7)) << 3) + tg * 2);
            }
#pragma unroll
            for (int ni = 0; ni < 4; ni++) {
                int rb = wn * 32 + ni * 8 + g;
                uint32_t b0 = *(const uint32_t*)(b_s + rb * 64 + (((2 * ks) ^ (rb & 7)) << 3) + tg * 2);
                uint32_t b1 = *(const uint32_t*)(b_s + rb * 64 + (((2 * ks + 1) ^ (rb & 7)) << 3) + tg * 2);
#pragma unroll
                for (int mi = 0; mi < 4; mi++)
                    mma_fp16(acc[mi][ni], a[mi], b0, b1);
            }
        }
    }

#pragma unroll
    for (int mi = 0; mi < 4; mi++) {
        int m0 = bm0 + wm * 64 + mi * 16 + g;
#pragma unroll
        for (int half = 0; half < 2; half++) {
            int m = m0 + half * 8;
            if (m >= M) continue;
            if (tok) {
                int t = tok[m]; float w = wt[m];
                float* dst = Out + (long long)t * N;
#pragma unroll
                for (int ni = 0; ni < 4; ni++) {
                    int n = bn0 + wn * 32 + ni * 8 + 2 * tg;
                    atomicAdd(&dst[n],     w * acc[mi][ni][half * 2 + 0]);
                    atomicAdd(&dst[n + 1], w * acc[mi][ni][half * 2 + 1]);
                }
            } else {
                float* dst = Out + (long long)m * N;
#pragma unroll
                for (int ni = 0; ni < 4; ni++) {
                    int n = bn0 + wn * 32 + ni * 8 + 2 * tg;
                    *reinterpret_cast<float2*>(&dst[n]) =
                        make_float2(acc[mi][ni][half * 2 + 0], acc[mi][ni][half * 2 + 1]);
                }
            }
        }
    }
}

// ---------------------------------------------------------------------------
// Launch
// ---------------------------------------------------------------------------
extern "C" void kernel_launch(void* const* d_in, const int* in_sizes, int n_in,
                              void* d_out, int out_size)
{
    (void)in_sizes; (void)n_in;
    const float* x      = (const float*)d_in[0];
    const float* gate_w = (const float*)d_in[1];
    const float* gate_b = (const float*)d_in[2];
    const float* w_gate = (const float*)d_in[3];
    const float* w_up   = (const float*)d_in[4];
    const float* w_down = (const float*)d_in[5];
    const float* sg_w   = (const float*)d_in[6];
    const float* su_w   = (const float*)d_in[7];
    const float* sd_w   = (const float*)d_in[8];
    float* out = (float*)d_out;

    void *p_hbuf, *p_shbuf, *p_cnt, *p_etok, *p_ewt, *p_ids;
    void *p_cx, *p_wgT, *p_wuT, *p_wdT, *p_sgT, *p_suT, *p_sdT;
    cudaGetSymbolAddress(&p_hbuf, g_hbuf);
    cudaGetSymbolAddress(&p_shbuf, g_shbuf);
    cudaGetSymbolAddress(&p_cnt, g_cnt);
    cudaGetSymbolAddress(&p_etok, g_etok);
    cudaGetSymbolAddress(&p_ewt, g_ewt);
    cudaGetSymbolAddress(&p_ids, g_ids);
    cudaGetSymbolAddress(&p_cx, g_cx);
    cudaGetSymbolAddress(&p_wgT, g_wgT);
    cudaGetSymbolAddress(&p_wuT, g_wuT);
    cudaGetSymbolAddress(&p_wdT, g_wdT);
    cudaGetSymbolAddress(&p_sgT, g_sgT);
    cudaGetSymbolAddress(&p_suT, g_suT);
    cudaGetSymbolAddress(&p_sdT, g_sdT);

    const int gu_smem = 3 * (128 * 128 + 2 * 64 * 128);   // 98304
    const int dn_smem = 3 * (128 * 128 + 128 * 128);      // 98304
    static bool attr_done = false;
    if (!attr_done) {
        cudaFuncSetAttribute(gateup_kernel, cudaFuncAttributeMaxDynamicSharedMemorySize, gu_smem);
        cudaFuncSetAttribute(down_kernel, cudaFuncAttributeMaxDynamicSharedMemorySize, dn_smem);
        attr_done = true;
    }

    // 0) prep: x -> fp16; weights -> transposed [N][K] fp16
    {
        int n4 = (TT * HH) >> 2;
        conv_half_kernel<<<(n4 + 255) / 256, 256>>>((const float4*)x, (__half2*)p_cx, n4);
    }
    dim3 tb(32, 8);
    trans_half_kernel<<<dim3(II / 32, HH / 32, EE), tb>>>(w_gate, (__half*)p_wgT, HH, II);
    trans_half_kernel<<<dim3(II / 32, HH / 32, EE), tb>>>(w_up,   (__half*)p_wuT, HH, II);
    trans_half_kernel<<<dim3(HH / 32, II / 32, EE), tb>>>(w_down, (__half*)p_wdT, II, HH);
    trans_half_kernel<<<dim3(ISH / 32, HH / 32, 1), tb>>>(sg_w, (__half*)p_sgT, HH, ISH);
    trans_half_kernel<<<dim3(ISH / 32, HH / 32, 1), tb>>>(su_w, (__half*)p_suT, HH, ISH);
    trans_half_kernel<<<dim3(HH / 32, ISH / 32, 1), tb>>>(sd_w, (__half*)p_sdT, ISH, HH);

    // 1) routing
    reset_cnt_kernel<<<1, 32>>>((int*)p_cnt);
    router_kernel<<<TT / 8, 256>>>(x, gate_w, gate_b,
                                   (int*)p_ids, (int*)p_cnt,
                                   (int*)p_etok, (float*)p_ewt);

    // 2) shared expert
    gateup_kernel<<<dim3(TT / 128, ISH / 64, 1), 256, gu_smem>>>(
        (const __half*)p_cx, nullptr, 0, nullptr, TT,
        (const __half*)p_sgT, (const __half*)p_suT, 0, ISH,
        (__half*)p_shbuf, 0);
    down_kernel<<<dim3(TT / 128, HH / 128, 1), 256, dn_smem>>>(
        (const __half*)p_shbuf, 0, ISH,
        (const __half*)p_sdT, 0, HH,
        nullptr, TT, nullptr, nullptr, 0, out);

    // 3) routed experts
    gateup_kernel<<<dim3(TT / 128, II / 64, EE), 256, gu_smem>>>(
        (const __half*)p_cx, (const int*)p_etok, TT, (const int*)p_cnt, 0,
        (const __half*)p_wgT, (const __half*)p_wuT, (long long)HH * II, II,
        (__half*)p_hbuf, (long long)TT * II);
    down_kernel<<<dim3(TT / 128, HH / 128, EE), 256, dn_smem>>>(
        (const __half*)p_hbuf, (long long)TT * II, II,
        (const __half*)p_wdT, (long long)II * HH, HH,
        (const int*)p_cnt, 0,
        (const int*)p_etok, (const float*)p_ewt, TT, out);

    // 4) topk_ids tail (value-cast), if present in out buffer
    long long main_sz = (long long)TT * HH;
    if ((long long)out_size > main_sz) {
        long long tail = (long long)out_size - main_sz;
        int n = (int)((tail < (long long)TT * TOPK) ? tail : (long long)TT * TOPK);
        ids_to_float_kernel<<<(n + 255) / 256, 256>>>((const int*)p_ids, out + main_sz, n);
    }
}

// round 12
// speedup vs baseline: 2.2146x; 1.0728x over previous
#include <cuda_runtime.h>
#include <cuda_fp16.h>
#include <math.h>
#include <stdint.h>

// Problem constants
#define TT   8192
#define HH   2048
#define EE   32
#define TOPK 8
#define II   1024
#define ISH  2048   // NSH * I

// ---------------------------------------------------------------------------
// Scratch (static __device__ — no allocations allowed)
// ---------------------------------------------------------------------------
__device__ __half g_hbuf[(long long)EE * TT * II];   // per-expert h (fp16)
__device__ __half g_shbuf[(long long)TT * ISH];      // shared h (fp16)
__device__ int    g_cnt[EE];
__device__ int    g_etok[EE * TT];
__device__ float  g_ewt[EE * TT];
__device__ int    g_ids[TT * TOPK];

// fp16 operands; weights TRANSPOSED to [N][K] K-major
__device__ __half g_cx[(long long)TT * HH];
__device__ __half g_wgT[(long long)EE * II * HH];    // [e][I][H]
__device__ __half g_wuT[(long long)EE * II * HH];    // [e][I][H]
__device__ __half g_wdT[(long long)EE * HH * II];    // [e][H][I]
__device__ __half g_sgT[(long long)ISH * HH];
__device__ __half g_suT[(long long)ISH * HH];
__device__ __half g_sdT[(long long)HH * ISH];

// ---------------------------------------------------------------------------
// Helpers
// ---------------------------------------------------------------------------
__device__ __forceinline__ uint32_t smem_u32(const void* p) {
    return (uint32_t)__cvta_generic_to_shared(p);
}
__device__ __forceinline__ void cpa16(uint32_t dst, const void* src) {
    asm volatile("cp.async.cg.shared.global [%0], [%1], 16;\n" :: "r"(dst), "l"(src));
}
__device__ __forceinline__ void cpa_commit() {
    asm volatile("cp.async.commit_group;\n");
}
template<int N> __device__ __forceinline__ void cpa_wait() {
    asm volatile("cp.async.wait_group %0;\n" :: "n"(N));
}

// m16n8k16 fp16 MMA, fp32 accumulate
__device__ __forceinline__ void mma_fp16(float* c, const uint32_t* a, uint32_t b0, uint32_t b1) {
    asm volatile(
        "mma.sync.aligned.m16n8k16.row.col.f32.f16.f16.f32 "
        "{%0,%1,%2,%3}, {%4,%5,%6,%7}, {%8,%9}, {%0,%1,%2,%3};\n"
        : "+f"(c[0]), "+f"(c[1]), "+f"(c[2]), "+f"(c[3])
        : "r"(a[0]), "r"(a[1]), "r"(a[2]), "r"(a[3]), "r"(b0), "r"(b1));
}

// ldmatrix x4 (non-transposed)
__device__ __forceinline__ void ldsm_x4(uint32_t* r, uint32_t addr) {
    asm volatile("ldmatrix.sync.aligned.m8n8.x4.shared.b16 {%0,%1,%2,%3}, [%4];"
                 : "=r"(r[0]), "=r"(r[1]), "=r"(r[2]), "=r"(r[3]) : "r"(addr));
}

// smem tiles: rows of 64 halves (128B) in 8 x 16B chunks;
// physical chunk = logical chunk ^ (row & 7).  Conflict-free for cp.async
// stores and for LDSM row-address sets.
__device__ __forceinline__ uint32_t tile_off(int row, int chunk16) {
    return (uint32_t)(row * 128 + ((chunk16 ^ (row & 7)) << 4));
}

// ---------------------------------------------------------------------------
// Prep kernels
// ---------------------------------------------------------------------------
__global__ __launch_bounds__(256) void conv_half_kernel(
    const float4* __restrict__ src, __half2* __restrict__ dst, int n4)
{
    int i = blockIdx.x * blockDim.x + threadIdx.x;
    if (i < n4) {
        float4 v = src[i];
        dst[i * 2 + 0] = __floats2half2_rn(v.x, v.y);
        dst[i * 2 + 1] = __floats2half2_rn(v.z, v.w);
    }
}

// [K][N] fp32 -> [N][K] fp16 transpose; 32(n) x 64(k) tiles, full-warp half2 writes
__global__ __launch_bounds__(256) void trans_half_kernel(
    const float* __restrict__ src, __half* __restrict__ dst, int K, int N)
{
    __shared__ float tb[64][33];
    long long base = (long long)blockIdx.z * K * (long long)N;
    int n0 = blockIdx.x * 32, k0 = blockIdx.y * 64;
    int tx = threadIdx.x, ty = threadIdx.y;
#pragma unroll
    for (int i = 0; i < 8; i++) {
        int kr = ty + i * 8;
        tb[kr][tx] = src[base + (long long)(k0 + kr) * N + n0 + tx];
    }
    __syncthreads();
#pragma unroll
    for (int i = 0; i < 4; i++) {
        int nr = ty + i * 8;
        __half2 v = __floats2half2_rn(tb[2 * tx][nr], tb[2 * tx + 1][nr]);
        *reinterpret_cast<__half2*>(&dst[base + (long long)(n0 + nr) * K + k0 + 2 * tx]) = v;
    }
}

// ---------------------------------------------------------------------------
// Router
// ---------------------------------------------------------------------------
__global__ __launch_bounds__(256) void router_kernel(
    const float* __restrict__ X, const float* __restrict__ GW,
    const float* __restrict__ GB,
    int* __restrict__ ids, int* __restrict__ cnt,
    int* __restrict__ etok, float* __restrict__ ewt)
{
    int warp = threadIdx.x >> 5;
    int lane = threadIdx.x & 31;
    int t = blockIdx.x * 8 + warp;
    if (t >= TT) return;

    const float* xr = X + (long long)t * HH;
    float acc = 0.f;
#pragma unroll 4
    for (int h = 0; h < HH; h++)
        acc = fmaf(xr[h], GW[h * EE + lane], acc);

    float score = 1.f / (1.f + expf(-acc));
    float ch = score + GB[lane];

    int kid[TOPK];
    float kw[TOPK];
    float wsum = 0.f;
#pragma unroll
    for (int k = 0; k < TOPK; k++) {
        float bv = ch; int bi = lane;
#pragma unroll
        for (int off = 16; off > 0; off >>= 1) {
            float ov = __shfl_down_sync(0xffffffffu, bv, off);
            int   oi = __shfl_down_sync(0xffffffffu, bi, off);
            if (ov > bv || (ov == bv && oi < bi)) { bv = ov; bi = oi; }
        }
        bi = __shfl_sync(0xffffffffu, bi, 0);
        float ws = __shfl_sync(0xffffffffu, score, bi);
        if (lane == bi) ch = -1e30f;
        kid[k] = bi; kw[k] = ws; wsum += ws;
    }

    if (lane == 0) {
        float norm = 2.5f / (wsum + 1e-20f);
#pragma unroll
        for (int k = 0; k < TOPK; k++) {
            int e = kid[k];
            ids[t * TOPK + k] = e;
            int pos = atomicAdd(&cnt[e], 1);
            etok[e * TT + pos] = t;
            ewt[e * TT + pos] = kw[k] * norm;
        }
    }
}

__global__ void reset_cnt_kernel(int* cnt) {
    if (threadIdx.x < EE) cnt[threadIdx.x] = 0;
}
__global__ void ids_to_float_kernel(const int* __restrict__ ids, float* __restrict__ dst, int n) {
    int i = blockIdx.x * blockDim.x + threadIdx.x;
    if (i < n) dst[i] = (float)ids[i];
}

// ---------------------------------------------------------------------------
// Fused gate+up GEMM (fp16 HMMA + LDSM): C = fp16(silu(A@BgT^T) * (A@BuT^T))
// Block 128x64 (G and U), BK=64, ST=3 (32KB/stage -> 2 CTAs/SM).
// Warps 4(M)x2(N); warp 32x32 of G and 32x32 of U.
// ---------------------------------------------------------------------------
__global__ __launch_bounds__(256, 2) void gateup_kernel(
    const __half* __restrict__ X,
    const int* __restrict__ idx_base, int idx_stride,
    const int* __restrict__ cntp, int Mfixed,
    const __half* __restrict__ BgT_base, const __half* __restrict__ BuT_base, long long bstride,
    int N, __half* __restrict__ C_base, long long cstride)
{
    constexpr int KD = HH, BK = 64, NK = KD / BK, ST = 3;
    constexpr int ABYTES = 128 * 128;   // 128 rows x 128B
    constexpr int BBYTES = 64 * 128;    // 64 rows x 128B

    int e = blockIdx.z;
    int M = cntp ? cntp[e] : Mfixed;
    int bm0 = blockIdx.x * 128;
    if (bm0 >= M) return;
    int bn0 = blockIdx.y * 64;

    const int*    idx = idx_base ? idx_base + (long long)e * idx_stride : nullptr;
    const __half* BgT = BgT_base + (long long)e * bstride;
    const __half* BuT = BuT_base + (long long)e * bstride;
    __half*       C   = C_base + (long long)e * cstride;

    extern __shared__ char smem[];
    uint32_t sA = smem_u32(smem);                        // ST x 16KB
    uint32_t sG = sA + ST * ABYTES;                      // ST x 8KB
    uint32_t sU = sG + ST * BBYTES;                      // ST x 8KB

    const int tid = threadIdx.x;
    const int lane = tid & 31, warp = tid >> 5;
    const int g = lane >> 2, tg = lane & 3;
    const int wm = warp & 3, wn = warp >> 2;

    // LDSM lane decomposition
    const int sel = lane >> 3, lr = lane & 7;
    const int ahi = sel >> 1;                 // A chunk +1 bit
    const uint32_t a_lane = (uint32_t)((wm * 32 + ((sel & 1) << 3) + lr) * 128);
    const int bklo = sel & 1;                 // B chunk bit
    const uint32_t b_lane = (uint32_t)((wn * 32 + ((sel >> 1) << 3) + lr) * 128);

    // cp.async mappings: A 1024 granules (4/thr), G/U 512 (2/thr)
    const __half* asrc[4]; uint32_t adst[4];
#pragma unroll
    for (int i = 0; i < 4; i++) {
        int li = tid + i * 256; int r = li & 127, c = li >> 7;
        int gm = bm0 + r; if (gm > M - 1) gm = M - 1;
        long long row = idx ? (long long)idx[gm] : (long long)gm;
        asrc[i] = X + row * KD + c * 8;
        adst[i] = sA + tile_off(r, c);
    }
    const __half* gsrc[2]; const __half* usrc[2]; uint32_t gdst[2], udst[2];
#pragma unroll
    for (int i = 0; i < 2; i++) {
        int li = tid + i * 256; int r = li & 63, c = li >> 6;
        gsrc[i] = BgT + (long long)(bn0 + r) * KD + c * 8;
        usrc[i] = BuT + (long long)(bn0 + r) * KD + c * 8;
        gdst[i] = sG + tile_off(r, c);
        udst[i] = sU + tile_off(r, c);
    }

    auto load_stage = [&](int t, int s) {
        int kf = t * BK;
#pragma unroll
        for (int i = 0; i < 4; i++) cpa16(adst[i] + s * ABYTES, asrc[i] + kf);
#pragma unroll
        for (int i = 0; i < 2; i++) {
            cpa16(gdst[i] + s * BBYTES, gsrc[i] + kf);
            cpa16(udst[i] + s * BBYTES, usrc[i] + kf);
        }
        cpa_commit();
    };

    load_stage(0, 0);
    load_stage(1, 1);

    float accG[2][4][4], accU[2][4][4];
#pragma unroll
    for (int a = 0; a < 2; a++)
#pragma unroll
        for (int b = 0; b < 4; b++)
#pragma unroll
            for (int c = 0; c < 4; c++) { accG[a][b][c] = 0.f; accU[a][b][c] = 0.f; }

    for (int k = 0; k < NK; k++) {
        if (k == NK - 1) cpa_wait<0>(); else cpa_wait<1>();
        __syncthreads();
        if (k + 2 < NK) load_stage(k + 2, (k + 2) % ST);

        uint32_t aST = sA + (k % ST) * ABYTES;
        uint32_t gST = sG + (k % ST) * BBYTES;
        uint32_t uST = sU + (k % ST) * BBYTES;

#pragma unroll
        for (int ks = 0; ks < BK / 16; ks++) {
            uint32_t a[2][4];
            uint32_t achunk = (uint32_t)(((2 * ks + ahi) ^ lr) << 4);
#pragma unroll
            for (int mi = 0; mi < 2; mi++)
                ldsm_x4(a[mi], aST + a_lane + mi * 2048 + achunk);

            uint32_t bchunk = (uint32_t)(((2 * ks + bklo) ^ lr) << 4);
#pragma unroll
            for (int p = 0; p < 2; p++) {
                uint32_t gb[4], ub[4];
                ldsm_x4(gb, gST + b_lane + p * 2048 + bchunk);
                ldsm_x4(ub, uST + b_lane + p * 2048 + bchunk);
#pragma unroll
                for (int mi = 0; mi < 2; mi++) {
                    mma_fp16(accG[mi][2 * p + 0], a[mi], gb[0], gb[1]);
                    mma_fp16(accG[mi][2 * p + 1], a[mi], gb[2], gb[3]);
                    mma_fp16(accU[mi][2 * p + 0], a[mi], ub[0], ub[1]);
                    mma_fp16(accU[mi][2 * p + 1], a[mi], ub[2], ub[3]);
                }
            }
        }
    }

    // epilogue: h = fp16(silu(g)*u), half2 stores
#pragma unroll
    for (int mi = 0; mi < 2; mi++) {
#pragma unroll
        for (int ni = 0; ni < 4; ni++) {
            int m0 = bm0 + wm * 32 + mi * 16 + g;
            int n0 = bn0 + wn * 32 + ni * 8 + 2 * tg;
#pragma unroll
            for (int half = 0; half < 2; half++) {
                int m = m0 + half * 8;
                if (m < M) {
                    float gv0 = accG[mi][ni][half * 2 + 0], uv0 = accU[mi][ni][half * 2 + 0];
                    float gv1 = accG[mi][ni][half * 2 + 1], uv1 = accU[mi][ni][half * 2 + 1];
                    float h0 = gv0 / (1.f + expf(-gv0)) * uv0;
                    float h1 = gv1 / (1.f + expf(-gv1)) * uv1;
                    *reinterpret_cast<__half2*>(&C[(long long)m * N + n0]) = __floats2half2_rn(h0, h1);
                }
            }
        }
    }
}

// ---------------------------------------------------------------------------
// Down-proj GEMM (fp16 HMMA + LDSM). Block 128x128, BK=64, ST=3.
// Warps 2(M)x4(N); warp 64x32.
// Routed: atomicAdd(out[tok[m]], wt[m]*d). Shared: float2 direct store.
// ---------------------------------------------------------------------------
__global__ __launch_bounds__(256, 2) void down_kernel(
    const __half* __restrict__ A_base, long long astride, int K,
    const __half* __restrict__ BT_base, long long bstride, int N,
    const int* __restrict__ cntp, int Mfixed,
    const int* __restrict__ tok_base, const float* __restrict__ wt_base, int tw_stride,
    float* __restrict__ Out)
{
    constexpr int BK = 64, ST = 3;
    constexpr int ABYTES = 128 * 128;
    constexpr int BBYTES = 128 * 128;

    int e = blockIdx.z;
    int M = cntp ? cntp[e] : Mfixed;
    int bm0 = blockIdx.x * 128;
    if (bm0 >= M) return;
    int bn0 = blockIdx.y * 128;
    const int NK = K / BK;

    const __half* A  = A_base + (long long)e * astride;
    const __half* BT = BT_base + (long long)e * bstride;
    const int*    tok = tok_base ? tok_base + (long long)e * tw_stride : nullptr;
    const float*  wt  = wt_base  ? wt_base  + (long long)e * tw_stride : nullptr;

    extern __shared__ char smem[];
    uint32_t sA = smem_u32(smem);
    uint32_t sB = sA + ST * ABYTES;

    const int tid = threadIdx.x;
    const int lane = tid & 31, warp = tid >> 5;
    const int g = lane >> 2, tg = lane & 3;
    const int wm = warp & 1, wn = warp >> 1;

    const int sel = lane >> 3, lr = lane & 7;
    const int ahi = sel >> 1;
    const uint32_t a_lane = (uint32_t)((wm * 64 + ((sel & 1) << 3) + lr) * 128);
    const int bklo = sel & 1;
    const uint32_t b_lane = (uint32_t)((wn * 32 + ((sel >> 1) << 3) + lr) * 128);

    const __half* asrc[4]; uint32_t adst[4];
    const __half* bsrc[4]; uint32_t bdst[4];
#pragma unroll
    for (int i = 0; i < 4; i++) {
        int li = tid + i * 256; int r = li & 127, c = li >> 7;
        int gm = bm0 + r;                           // within expert capacity
        asrc[i] = A + (long long)gm * K + c * 8;
        adst[i] = sA + tile_off(r, c);
        bsrc[i] = BT + (long long)(bn0 + r) * K + c * 8;
        bdst[i] = sB + tile_off(r, c);
    }

    auto load_stage = [&](int t, int s) {
        int kf = t * BK;
#pragma unroll
        for (int i = 0; i < 4; i++) {
            cpa16(adst[i] + s * ABYTES, asrc[i] + kf);
            cpa16(bdst[i] + s * BBYTES, bsrc[i] + kf);
        }
        cpa_commit();
    };

    load_stage(0, 0);
    load_stage(1, 1);

    float acc[4][4][4];
#pragma unroll
    for (int a = 0; a < 4; a++)
#pragma unroll
        for (int b = 0; b < 4; b++)
#pragma unroll
            for (int c = 0; c < 4; c++) acc[a][b][c] = 0.f;

    for (int k = 0; k < NK; k++) {
        if (k == NK - 1) cpa_wait<0>(); else cpa_wait<1>();
        __syncthreads();
        if (k + 2 < NK) load_stage(k + 2, (k + 2) % ST);

        uint32_t aST = sA + (k % ST) * ABYTES;
        uint32_t bST = sB + (k % ST) * BBYTES;

#pragma unroll
        for (int ks = 0; ks < BK / 16; ks++) {
            uint32_t a[4][4];
            uint32_t achunk = (uint32_t)(((2 * ks + ahi) ^ lr) << 4);
#pragma unroll
            for (int mi = 0; mi < 4; mi++)
                ldsm_x4(a[mi], aST + a_lane + mi * 2048 + achunk);

            uint32_t bchunk = (uint32_t)(((2 * ks + bklo) ^ lr) << 4);
#pragma unroll
            for (int p = 0; p < 2; p++) {
                uint32_t bb[4];
                ldsm_x4(bb, bST + b_lane + p * 2048 + bchunk);
#pragma unroll
                for (int mi = 0; mi < 4; mi++) {
                    mma_fp16(acc[mi][2 * p + 0], a[mi], bb[0], bb[1]);
                    mma_fp16(acc[mi][2 * p + 1], a[mi], bb[2], bb[3]);
                }
            }
        }
    }

#pragma unroll
    for (int mi = 0; mi < 4; mi++) {
        int m0 = bm0 + wm * 64 + mi * 16 + g;
#pragma unroll
        for (int half = 0; half < 2; half++) {
            int m = m0 + half * 8;
            if (m >= M) continue;
            if (tok) {
                int t = tok[m]; float w = wt[m];
                float* dst = Out + (long long)t * N;
#pragma unroll
                for (int ni = 0; ni < 4; ni++) {
                    int n = bn0 + wn * 32 + ni * 8 + 2 * tg;
                    atomicAdd(&dst[n],     w * acc[mi][ni][half * 2 + 0]);
                    atomicAdd(&dst[n + 1], w * acc[mi][ni][half * 2 + 1]);
                }
            } else {
                float* dst = Out + (long long)m * N;
#pragma unroll
                for (int ni = 0; ni < 4; ni++) {
                    int n = bn0 + wn * 32 + ni * 8 + 2 * tg;
                    *reinterpret_cast<float2*>(&dst[n]) =
                        make_float2(acc[mi][ni][half * 2 + 0], acc[mi][ni][half * 2 + 1]);
                }
            }
        }
    }
}

// ---------------------------------------------------------------------------
// Launch
// ---------------------------------------------------------------------------
extern "C" void kernel_launch(void* const* d_in, const int* in_sizes, int n_in,
                              void* d_out, int out_size)
{
    (void)in_sizes; (void)n_in;
    const float* x      = (const float*)d_in[0];
    const float* gate_w = (const float*)d_in[1];
    const float* gate_b = (const float*)d_in[2];
    const float* w_gate = (const float*)d_in[3];
    const float* w_up   = (const float*)d_in[4];
    const float* w_down = (const float*)d_in[5];
    const float* sg_w   = (const float*)d_in[6];
    const float* su_w   = (const float*)d_in[7];
    const float* sd_w   = (const float*)d_in[8];
    float* out = (float*)d_out;

    void *p_hbuf, *p_shbuf, *p_cnt, *p_etok, *p_ewt, *p_ids;
    void *p_cx, *p_wgT, *p_wuT, *p_wdT, *p_sgT, *p_suT, *p_sdT;
    cudaGetSymbolAddress(&p_hbuf, g_hbuf);
    cudaGetSymbolAddress(&p_shbuf, g_shbuf);
    cudaGetSymbolAddress(&p_cnt, g_cnt);
    cudaGetSymbolAddress(&p_etok, g_etok);
    cudaGetSymbolAddress(&p_ewt, g_ewt);
    cudaGetSymbolAddress(&p_ids, g_ids);
    cudaGetSymbolAddress(&p_cx, g_cx);
    cudaGetSymbolAddress(&p_wgT, g_wgT);
    cudaGetSymbolAddress(&p_wuT, g_wuT);
    cudaGetSymbolAddress(&p_wdT, g_wdT);
    cudaGetSymbolAddress(&p_sgT, g_sgT);
    cudaGetSymbolAddress(&p_suT, g_suT);
    cudaGetSymbolAddress(&p_sdT, g_sdT);

    const int gu_smem = 3 * (128 * 128 + 2 * 64 * 128);   // 98304
    const int dn_smem = 3 * (128 * 128 + 128 * 128);      // 98304
    static bool attr_done = false;
    if (!attr_done) {
        cudaFuncSetAttribute(gateup_kernel, cudaFuncAttributeMaxDynamicSharedMemorySize, gu_smem);
        cudaFuncSetAttribute(down_kernel, cudaFuncAttributeMaxDynamicSharedMemorySize, dn_smem);
        attr_done = true;
    }

    // 0) prep: x -> fp16; weights -> transposed [N][K] fp16
    {
        int n4 = (TT * HH) >> 2;
        conv_half_kernel<<<(n4 + 255) / 256, 256>>>((const float4*)x, (__half2*)p_cx, n4);
    }
    dim3 tb(32, 8);
    trans_half_kernel<<<dim3(II / 32, HH / 64, EE), tb>>>(w_gate, (__half*)p_wgT, HH, II);
    trans_half_kernel<<<dim3(II / 32, HH / 64, EE), tb>>>(w_up,   (__half*)p_wuT, HH, II);
    trans_half_kernel<<<dim3(HH / 32, II / 64, EE), tb>>>(w_down, (__half*)p_wdT, II, HH);
    trans_half_kernel<<<dim3(ISH / 32, HH / 64, 1), tb>>>(sg_w, (__half*)p_sgT, HH, ISH);
    trans_half_kernel<<<dim3(ISH / 32, HH / 64, 1), tb>>>(su_w, (__half*)p_suT, HH, ISH);
    trans_half_kernel<<<dim3(HH / 32, ISH / 64, 1), tb>>>(sd_w, (__half*)p_sdT, ISH, HH);

    // 1) routing
    reset_cnt_kernel<<<1, 32>>>((int*)p_cnt);
    router_kernel<<<TT / 8, 256>>>(x, gate_w, gate_b,
                                   (int*)p_ids, (int*)p_cnt,
                                   (int*)p_etok, (float*)p_ewt);

    // 2) shared expert
    gateup_kernel<<<dim3(TT / 128, ISH / 64, 1), 256, gu_smem>>>(
        (const __half*)p_cx, nullptr, 0, nullptr, TT,
        (const __half*)p_sgT, (const __half*)p_suT, 0, ISH,
        (__half*)p_shbuf, 0);
    down_kernel<<<dim3(TT / 128, HH / 128, 1), 256, dn_smem>>>(
        (const __half*)p_shbuf, 0, ISH,
        (const __half*)p_sdT, 0, HH,
        nullptr, TT, nullptr, nullptr, 0, out);

    // 3) routed experts
    gateup_kernel<<<dim3(TT / 128, II / 64, EE), 256, gu_smem>>>(
        (const __half*)p_cx, (const int*)p_etok, TT, (const int*)p_cnt, 0,
        (const __half*)p_wgT, (const __half*)p_wuT, (long long)HH * II, II,
        (__half*)p_hbuf, (long long)TT * II);
    down_kernel<<<dim3(TT / 128, HH / 128, EE), 256, dn_smem>>>(
        (const __half*)p_hbuf, (long long)TT * II, II,
        (const __half*)p_wdT, (long long)II * HH, HH,
        (const int*)p_cnt, 0,
        (const int*)p_etok, (const float*)p_ewt, TT, out);

    // 4) topk_ids tail (value-cast), if present in out buffer
    long long main_sz = (long long)TT * HH;
    if ((long long)out_size > main_sz) {
        long long tail = (long long)out_size - main_sz;
        int n = (int)((tail < (long long)TT * TOPK) ? tail : (long long)TT * TOPK);
        ids_to_float_kernel<<<(n + 255) / 256, 256>>>((const int*)p_ids, out + main_sz, n);
    }
}

// round 17
// speedup vs baseline: 3.4063x; 1.5381x over previous
#include <cuda_runtime.h>
#include <cuda_fp16.h>
#include <math.h>
#include <stdint.h>

// Problem constants
#define TT   8192
#define HH   2048
#define EE   32
#define TOPK 8
#define II   1024
#define ISH  2048   // NSH * I

// ---------------------------------------------------------------------------
// Scratch (static __device__ — no allocations allowed)
// ---------------------------------------------------------------------------
__device__ __half g_hbuf[(long long)EE * TT * II];   // per-expert h (fp16)
__device__ __half g_shbuf[(long long)TT * ISH];      // shared h (fp16)
__device__ int    g_cnt[EE];
__device__ int    g_etok[EE * TT];
__device__ float  g_ewt[EE * TT];
__device__ int    g_ids[TT * TOPK];
__device__ int    g_sched[160];                      // prefix/mt/M tables
__device__ int    g_ctr[2];                          // work counters

// fp16 operands; weights TRANSPOSED to [N][K] K-major
__device__ __half g_cx[(long long)TT * HH];
__device__ __half g_wgT[(long long)EE * II * HH];    // [e][I][H]
__device__ __half g_wuT[(long long)EE * II * HH];    // [e][I][H]
__device__ __half g_wdT[(long long)EE * HH * II];    // [e][H][I]
__device__ __half g_sgT[(long long)ISH * HH];
__device__ __half g_suT[(long long)ISH * HH];
__device__ __half g_sdT[(long long)HH * ISH];

// ---------------------------------------------------------------------------
// Helpers
// ---------------------------------------------------------------------------
__device__ __forceinline__ uint32_t smem_u32(const void* p) {
    return (uint32_t)__cvta_generic_to_shared(p);
}
__device__ __forceinline__ void cpa16(uint32_t dst, const void* src) {
    asm volatile("cp.async.cg.shared.global [%0], [%1], 16;\n" :: "r"(dst), "l"(src));
}
__device__ __forceinline__ void cpa_commit() {
    asm volatile("cp.async.commit_group;\n");
}
template<int N> __device__ __forceinline__ void cpa_wait() {
    asm volatile("cp.async.wait_group %0;\n" :: "n"(N));
}
__device__ __forceinline__ void mma_fp16(float* c, const uint32_t* a, uint32_t b0, uint32_t b1) {
    asm volatile(
        "mma.sync.aligned.m16n8k16.row.col.f32.f16.f16.f32 "
        "{%0,%1,%2,%3}, {%4,%5,%6,%7}, {%8,%9}, {%0,%1,%2,%3};\n"
        : "+f"(c[0]), "+f"(c[1]), "+f"(c[2]), "+f"(c[3])
        : "r"(a[0]), "r"(a[1]), "r"(a[2]), "r"(a[3]), "r"(b0), "r"(b1));
}
__device__ __forceinline__ void ldsm_x4(uint32_t* r, uint32_t addr) {
    asm volatile("ldmatrix.sync.aligned.m8n8.x4.shared.b16 {%0,%1,%2,%3}, [%4];"
                 : "=r"(r[0]), "=r"(r[1]), "=r"(r[2]), "=r"(r[3]) : "r"(addr));
}
// rows of 64 halves (128B) in 8 x 16B chunks; phys chunk = chunk ^ (row&7)
__device__ __forceinline__ uint32_t tile_off(int row, int chunk16) {
    return (uint32_t)(row * 128 + ((chunk16 ^ (row & 7)) << 4));
}

// ---------------------------------------------------------------------------
// Prep kernels
// ---------------------------------------------------------------------------
__global__ __launch_bounds__(256) void conv_half_kernel(
    const float4* __restrict__ src, __half2* __restrict__ dst, int n4)
{
    int i = blockIdx.x * blockDim.x + threadIdx.x;
    if (i < n4) {
        float4 v = src[i];
        dst[i * 2 + 0] = __floats2half2_rn(v.x, v.y);
        dst[i * 2 + 1] = __floats2half2_rn(v.z, v.w);
    }
}

struct TJobs {
    const float* src[6];
    __half*      dst[6];
    int K[6], N[6], base[7];
};

// merged transpose: [K][N] fp32 -> [N][K] fp16 for all 6 weight groups
__global__ __launch_bounds__(256) void trans_all_kernel(TJobs J)
{
    __shared__ float tb[64][33];
    int bid = blockIdx.x;
    int j = 0;
    while (j < 5 && bid >= J.base[j + 1]) j++;
    int z = bid - J.base[j];
    int K = J.K[j], N = J.N[j];
    int tiles = (N / 32) * (K / 64);
    int e = z / tiles, r = z % tiles;
    int n0 = (r % (N / 32)) * 32, k0 = (r / (N / 32)) * 64;
    long long base = (long long)e * K * (long long)N;
    const float* src = J.src[j];
    __half* dst = J.dst[j];
    int tx = threadIdx.x & 31, ty = threadIdx.x >> 5;
#pragma unroll
    for (int i = 0; i < 8; i++) {
        int kr = ty + i * 8;
        tb[kr][tx] = src[base + (long long)(k0 + kr) * N + n0 + tx];
    }
    __syncthreads();
#pragma unroll
    for (int i = 0; i < 4; i++) {
        int nr = ty + i * 8;
        __half2 v = __floats2half2_rn(tb[2 * tx][nr], tb[2 * tx + 1][nr]);
        *reinterpret_cast<__half2*>(&dst[base + (long long)(n0 + nr) * K + k0 + 2 * tx]) = v;
    }
}

// ---------------------------------------------------------------------------
// Router
// ---------------------------------------------------------------------------
__global__ __launch_bounds__(256) void router_kernel(
    const float* __restrict__ X, const float* __restrict__ GW,
    const float* __restrict__ GB,
    int* __restrict__ ids, int* __restrict__ cnt,
    int* __restrict__ etok, float* __restrict__ ewt)
{
    int warp = threadIdx.x >> 5;
    int lane = threadIdx.x & 31;
    int t = blockIdx.x * 8 + warp;
    if (t >= TT) return;

    const float* xr = X + (long long)t * HH;
    float acc = 0.f;
#pragma unroll 4
    for (int h = 0; h < HH; h++)
        acc = fmaf(xr[h], GW[h * EE + lane], acc);

    float score = 1.f / (1.f + expf(-acc));
    float ch = score + GB[lane];

    int kid[TOPK];
    float kw[TOPK];
    float wsum = 0.f;
#pragma unroll
    for (int k = 0; k < TOPK; k++) {
        float bv = ch; int bi = lane;
#pragma unroll
        for (int off = 16; off > 0; off >>= 1) {
            float ov = __shfl_down_sync(0xffffffffu, bv, off);
            int   oi = __shfl_down_sync(0xffffffffu, bi, off);
            if (ov > bv || (ov == bv && oi < bi)) { bv = ov; bi = oi; }
        }
        bi = __shfl_sync(0xffffffffu, bi, 0);
        float ws = __shfl_sync(0xffffffffu, score, bi);
        if (lane == bi) ch = -1e30f;
        kid[k] = bi; kw[k] = ws; wsum += ws;
    }

    if (lane == 0) {
        float norm = 2.5f / (wsum + 1e-20f);
#pragma unroll
        for (int k = 0; k < TOPK; k++) {
            int e = kid[k];
            ids[t * TOPK + k] = e;
            int pos = atomicAdd(&cnt[e], 1);
            etok[e * TT + pos] = t;
            ewt[e * TT + pos] = kw[k] * norm;
        }
    }
}

__global__ void reset_cnt_kernel(int* cnt) {
    if (threadIdx.x < EE) cnt[threadIdx.x] = 0;
}
__global__ void ids_to_float_kernel(const int* __restrict__ ids, float* __restrict__ dst, int n) {
    int i = blockIdx.x * blockDim.x + threadIdx.x;
    if (i < n) dst[i] = (float)ids[i];
}
__global__ void zero_out_kernel(float4* out, int n4) {
    int i = blockIdx.x * blockDim.x + threadIdx.x;
    if (i < n4) out[i] = make_float4(0.f, 0.f, 0.f, 0.f);
}

// build tile schedules + reset work counters. e==EE is the shared expert.
__global__ void sched_kernel(const int* __restrict__ cnt, int* __restrict__ sched,
                             int* __restrict__ ctr)
{
    if (threadIdx.x == 0) {
        int tg = 0, td = 0;
        for (int e = 0; e <= EE; e++) {
            int M = (e < EE) ? cnt[e] : TT;
            if (M < 0) M = 0;
            if (M > TT) M = TT;
            int mt = (M + 255) >> 8;
            int ng = (e < EE) ? (II / 64) : (ISH / 64);
            sched[e]       = tg;
            sched[40 + e]  = td;
            sched[80 + e]  = mt;
            sched[120 + e] = M;
            tg += mt * ng;
            td += mt * (HH / 128);
        }
        sched[33]      = tg;
        sched[40 + 33] = td;
        ctr[0] = 0; ctr[1] = 0;
    }
}

// ---------------------------------------------------------------------------
// Persistent gate+up GEMM. Tile 256 x (64 G + 64 U), BK=64, ST=3, 256 thr.
// Warps 4(M) x 2(N): warp 64x32 of G and U.
// ---------------------------------------------------------------------------
__global__ __launch_bounds__(256, 1) void gateup_all(
    const __half* __restrict__ X, const int* __restrict__ etok,
    const __half* __restrict__ wgT, const __half* __restrict__ wuT,
    const __half* __restrict__ sgT, const __half* __restrict__ suT,
    __half* __restrict__ hbuf, __half* __restrict__ shbuf,
    const int* __restrict__ sched, int* __restrict__ ctr)
{
    constexpr int BK = 64, NK = HH / BK, ST = 3;
    constexpr int ABYTES = 256 * 128;   // 32KB
    constexpr int BBYTES = 64 * 128;    // 8KB

    extern __shared__ char smem[];
    uint32_t sA = smem_u32(smem);
    uint32_t sG = sA + ST * ABYTES;
    uint32_t sU = sG + ST * BBYTES;

    __shared__ int s_pref[34], s_mt[33], s_M[33], s_t;

    const int tid = threadIdx.x;
    if (tid < 34) s_pref[tid] = sched[tid];
    if (tid < 33) { s_mt[tid] = sched[80 + tid]; s_M[tid] = sched[120 + tid]; }
    __syncthreads();
    const int total = s_pref[33];

    const int lane = tid & 31, warp = tid >> 5;
    const int g = lane >> 2, tg = lane & 3;
    const int wm = warp & 3, wn = warp >> 2;
    const int sel = lane >> 3, lr = lane & 7;
    const int ahi = sel >> 1;
    const uint32_t a_lane = (uint32_t)((wm * 64 + ((sel & 1) << 3) + lr) * 128);
    const int bklo = sel & 1;
    const uint32_t b_lane = (uint32_t)((wn * 32 + ((sel >> 1) << 3) + lr) * 128);

    for (;;) {
        __syncthreads();
        if (tid == 0) s_t = atomicAdd(&ctr[0], 1);
        __syncthreads();
        int t = s_t;
        if (t >= total) break;

        int e = 0;
        while (e < EE && t >= s_pref[e + 1]) e++;
        int local = t - s_pref[e];
        int mt = s_mt[e];
        int m_tile = local % mt, n_tile = local / mt;
        int bm0 = m_tile * 256, bn0 = n_tile * 64;

        const int* idx; int M, N;
        const __half *Bg, *Bu; __half* C;
        if (e < EE) {
            idx = etok + (long long)e * TT; M = s_M[e]; N = II;
            Bg = wgT + (long long)e * HH * II;
            Bu = wuT + (long long)e * HH * II;
            C = hbuf + (long long)e * TT * II;
        } else {
            idx = nullptr; M = TT; N = ISH;
            Bg = sgT; Bu = suT; C = shbuf;
        }

        // per-tile load pointers (A: 8 granules/thr; G/U: 2 each)
        const __half* asrc[8]; uint32_t adst[8];
#pragma unroll
        for (int i = 0; i < 8; i++) {
            int li = tid + i * 256; int r = li >> 3, c = li & 7;
            int gm = bm0 + r; if (gm > M - 1) gm = M - 1;
            long long row = idx ? (long long)idx[gm] : (long long)gm;
            asrc[i] = X + row * HH + c * 8;
            adst[i] = sA + tile_off(r, c);
        }
        const __half* gsrc[2]; const __half* usrc[2]; uint32_t gdst[2], udst[2];
#pragma unroll
        for (int i = 0; i < 2; i++) {
            int li = tid + i * 256; int r = li >> 3, c = li & 7;
            gsrc[i] = Bg + (long long)(bn0 + r) * HH + c * 8;
            usrc[i] = Bu + (long long)(bn0 + r) * HH + c * 8;
            gdst[i] = sG + tile_off(r, c);
            udst[i] = sU + tile_off(r, c);
        }

        auto load_stage = [&](int kt, int s) {
            int kf = kt * BK;
#pragma unroll
            for (int i = 0; i < 8; i++) cpa16(adst[i] + s * ABYTES, asrc[i] + kf);
#pragma unroll
            for (int i = 0; i < 2; i++) {
                cpa16(gdst[i] + s * BBYTES, gsrc[i] + kf);
                cpa16(udst[i] + s * BBYTES, usrc[i] + kf);
            }
            cpa_commit();
        };

        load_stage(0, 0);
        load_stage(1, 1);

        float accG[4][4][4], accU[4][4][4];
#pragma unroll
        for (int a = 0; a < 4; a++)
#pragma unroll
            for (int b = 0; b < 4; b++)
#pragma unroll
                for (int c = 0; c < 4; c++) { accG[a][b][c] = 0.f; accU[a][b][c] = 0.f; }

        for (int k = 0; k < NK; k++) {
            if (k == NK - 1) cpa_wait<0>(); else cpa_wait<1>();
            __syncthreads();
            if (k + 2 < NK) load_stage(k + 2, (k + 2) % ST);

            uint32_t aST = sA + (k % ST) * ABYTES;
            uint32_t gST = sG + (k % ST) * BBYTES;
            uint32_t uST = sU + (k % ST) * BBYTES;

#pragma unroll
            for (int ks = 0; ks < BK / 16; ks++) {
                uint32_t a[4][4];
                uint32_t achunk = (uint32_t)(((2 * ks + ahi) ^ lr) << 4);
#pragma unroll
                for (int mi = 0; mi < 4; mi++)
                    ldsm_x4(a[mi], aST + a_lane + mi * 2048 + achunk);

                uint32_t bchunk = (uint32_t)(((2 * ks + bklo) ^ lr) << 4);
#pragma unroll
                for (int p = 0; p < 2; p++) {
                    uint32_t gb[4], ub[4];
                    ldsm_x4(gb, gST + b_lane + p * 2048 + bchunk);
                    ldsm_x4(ub, uST + b_lane + p * 2048 + bchunk);
#pragma unroll
                    for (int mi = 0; mi < 4; mi++) {
                        mma_fp16(accG[mi][2 * p + 0], a[mi], gb[0], gb[1]);
                        mma_fp16(accG[mi][2 * p + 1], a[mi], gb[2], gb[3]);
                        mma_fp16(accU[mi][2 * p + 0], a[mi], ub[0], ub[1]);
                        mma_fp16(accU[mi][2 * p + 1], a[mi], ub[2], ub[3]);
                    }
                }
            }
        }

        // epilogue: h = fp16(silu(g)*u)
#pragma unroll
        for (int mi = 0; mi < 4; mi++) {
#pragma unroll
            for (int ni = 0; ni < 4; ni++) {
                int m0 = bm0 + wm * 64 + mi * 16 + g;
                int n0 = bn0 + wn * 32 + ni * 8 + 2 * tg;
#pragma unroll
                for (int hf = 0; hf < 2; hf++) {
                    int m = m0 + hf * 8;
                    if (m < M) {
                        float gv0 = accG[mi][ni][hf * 2 + 0], uv0 = accU[mi][ni][hf * 2 + 0];
                        float gv1 = accG[mi][ni][hf * 2 + 1], uv1 = accU[mi][ni][hf * 2 + 1];
                        float h0 = gv0 / (1.f + expf(-gv0)) * uv0;
                        float h1 = gv1 / (1.f + expf(-gv1)) * uv1;
                        *reinterpret_cast<__half2*>(&C[(long long)m * N + n0]) =
                            __floats2half2_rn(h0, h1);
                    }
                }
            }
        }
    }
}

// ---------------------------------------------------------------------------
// Persistent down GEMM. Tile 256 x 128, BK=64, ST=3, 256 thr.
// Warps 4(M) x 2(N): warp 64x64. Output: atomicAdd into zeroed Out.
// ---------------------------------------------------------------------------
__global__ __launch_bounds__(256, 1) void down_all(
    const int* __restrict__ etok, const float* __restrict__ ewt,
    const __half* __restrict__ wdT, const __half* __restrict__ sdT,
    const __half* __restrict__ hbuf, const __half* __restrict__ shbuf,
    float* __restrict__ Out,
    const int* __restrict__ sched, int* __restrict__ ctr)
{
    constexpr int BK = 64, ST = 3;
    constexpr int ABYTES = 256 * 128;   // 32KB
    constexpr int BBYTES = 128 * 128;   // 16KB

    extern __shared__ char smem[];
    uint32_t sA = smem_u32(smem);
    uint32_t sB = sA + ST * ABYTES;

    __shared__ int s_pref[34], s_mt[33], s_M[33], s_t;

    const int tid = threadIdx.x;
    if (tid < 34) s_pref[tid] = sched[40 + tid];
    if (tid < 33) { s_mt[tid] = sched[80 + tid]; s_M[tid] = sched[120 + tid]; }
    __syncthreads();
    const int total = s_pref[33];

    const int lane = tid & 31, warp = tid >> 5;
    const int g = lane >> 2, tg = lane & 3;
    const int wm = warp & 3, wn = warp >> 2;
    const int sel = lane >> 3, lr = lane & 7;
    const int ahi = sel >> 1;
    const uint32_t a_lane = (uint32_t)((wm * 64 + ((sel & 1) << 3) + lr) * 128);
    const int bklo = sel & 1;
    const uint32_t b_lane = (uint32_t)((wn * 64 + ((sel >> 1) << 3) + lr) * 128);

    for (;;) {
        __syncthreads();
        if (tid == 0) s_t = atomicAdd(&ctr[1], 1);
        __syncthreads();
        int t = s_t;
        if (t >= total) break;

        int e = 0;
        while (e < EE && t >= s_pref[e + 1]) e++;
        int local = t - s_pref[e];
        int mt = s_mt[e];
        int m_tile = local % mt, n_tile = local / mt;
        int bm0 = m_tile * 256, bn0 = n_tile * 128;

        int M, K;
        const __half *A, *B;
        const int* tok; const float* wt;
        if (e < EE) {
            M = s_M[e]; K = II;
            A = hbuf + (long long)e * TT * II;
            B = wdT + (long long)e * HH * II;
            tok = etok + (long long)e * TT;
            wt = ewt + (long long)e * TT;
        } else {
            M = TT; K = ISH;
            A = shbuf; B = sdT; tok = nullptr; wt = nullptr;
        }
        const int NK = K / BK;

        const __half* asrc[8]; uint32_t adst[8];
#pragma unroll
        for (int i = 0; i < 8; i++) {
            int li = tid + i * 256; int r = li >> 3, c = li & 7;
            asrc[i] = A + (long long)(bm0 + r) * K + c * 8;
            adst[i] = sA + tile_off(r, c);
        }
        const __half* bsrc[4]; uint32_t bdst[4];
#pragma unroll
        for (int i = 0; i < 4; i++) {
            int li = tid + i * 256; int r = li >> 3, c = li & 7;
            bsrc[i] = B + (long long)(bn0 + r) * K + c * 8;
            bdst[i] = sB + tile_off(r, c);
        }

        auto load_stage = [&](int kt, int s) {
            int kf = kt * BK;
#pragma unroll
            for (int i = 0; i < 8; i++) cpa16(adst[i] + s * ABYTES, asrc[i] + kf);
#pragma unroll
            for (int i = 0; i < 4; i++) cpa16(bdst[i] + s * BBYTES, bsrc[i] + kf);
            cpa_commit();
        };

        load_stage(0, 0);
        load_stage(1, 1);

        float acc[4][8][4];
#pragma unroll
        for (int a = 0; a < 4; a++)
#pragma unroll
            for (int b = 0; b < 8; b++)
#pragma unroll
                for (int c = 0; c < 4; c++) acc[a][b][c] = 0.f;

        for (int k = 0; k < NK; k++) {
            if (k == NK - 1) cpa_wait<0>(); else cpa_wait<1>();
            __syncthreads();
            if (k + 2 < NK) load_stage(k + 2, (k + 2) % ST);

            uint32_t aST = sA + (k % ST) * ABYTES;
            uint32_t bST = sB + (k % ST) * BBYTES;

#pragma unroll
            for (int ks = 0; ks < BK / 16; ks++) {
                uint32_t a[4][4];
                uint32_t achunk = (uint32_t)(((2 * ks + ahi) ^ lr) << 4);
#pragma unroll
                for (int mi = 0; mi < 4; mi++)
                    ldsm_x4(a[mi], aST + a_lane + mi * 2048 + achunk);

                uint32_t bchunk = (uint32_t)(((2 * ks + bklo) ^ lr) << 4);
#pragma unroll
                for (int p = 0; p < 4; p++) {
                    uint32_t bb[4];
                    ldsm_x4(bb, bST + b_lane + p * 2048 + bchunk);
#pragma unroll
                    for (int mi = 0; mi < 4; mi++) {
                        mma_fp16(acc[mi][2 * p + 0], a[mi], bb[0], bb[1]);
                        mma_fp16(acc[mi][2 * p + 1], a[mi], bb[2], bb[3]);
                    }
                }
            }
        }

#pragma unroll
        for (int mi = 0; mi < 4; mi++) {
            int m0 = bm0 + wm * 64 + mi * 16 + g;
#pragma unroll
            for (int hf = 0; hf < 2; hf++) {
                int m = m0 + hf * 8;
                if (m >= M) continue;
                int row; float w;
                if (tok) { row = tok[m]; w = wt[m]; }
                else     { row = m;      w = 1.f;   }
                float* dst = Out + (long long)row * HH;
#pragma unroll
                for (int ni = 0; ni < 8; ni++) {
                    int n = bn0 + wn * 64 + ni * 8 + 2 * tg;
                    atomicAdd(&dst[n],     w * acc[mi][ni][hf * 2 + 0]);
                    atomicAdd(&dst[n + 1], w * acc[mi][ni][hf * 2 + 1]);
                }
            }
        }
    }
}

// ---------------------------------------------------------------------------
// Launch
// ---------------------------------------------------------------------------
extern "C" void kernel_launch(void* const* d_in, const int* in_sizes, int n_in,
                              void* d_out, int out_size)
{
    (void)in_sizes; (void)n_in;
    const float* x      = (const float*)d_in[0];
    const float* gate_w = (const float*)d_in[1];
    const float* gate_b = (const float*)d_in[2];
    const float* w_gate = (const float*)d_in[3];
    const float* w_up   = (const float*)d_in[4];
    const float* w_down = (const float*)d_in[5];
    const float* sg_w   = (const float*)d_in[6];
    const float* su_w   = (const float*)d_in[7];
    const float* sd_w   = (const float*)d_in[8];
    float* out = (float*)d_out;

    void *p_hbuf, *p_shbuf, *p_cnt, *p_etok, *p_ewt, *p_ids, *p_sched, *p_ctr;
    void *p_cx, *p_wgT, *p_wuT, *p_wdT, *p_sgT, *p_suT, *p_sdT;
    cudaGetSymbolAddress(&p_hbuf, g_hbuf);
    cudaGetSymbolAddress(&p_shbuf, g_shbuf);
    cudaGetSymbolAddress(&p_cnt, g_cnt);
    cudaGetSymbolAddress(&p_etok, g_etok);
    cudaGetSymbolAddress(&p_ewt, g_ewt);
    cudaGetSymbolAddress(&p_ids, g_ids);
    cudaGetSymbolAddress(&p_sched, g_sched);
    cudaGetSymbolAddress(&p_ctr, g_ctr);
    cudaGetSymbolAddress(&p_cx, g_cx);
    cudaGetSymbolAddress(&p_wgT, g_wgT);
    cudaGetSymbolAddress(&p_wuT, g_wuT);
    cudaGetSymbolAddress(&p_wdT, g_wdT);
    cudaGetSymbolAddress(&p_sgT, g_sgT);
    cudaGetSymbolAddress(&p_suT, g_suT);
    cudaGetSymbolAddress(&p_sdT, g_sdT);

    const int gemm_smem = 3 * (256 * 128 + 2 * 64 * 128);   // 147456 (both)
    static int num_sms = 0;
    if (num_sms == 0) {
        cudaFuncSetAttribute(gateup_all, cudaFuncAttributeMaxDynamicSharedMemorySize, gemm_smem);
        cudaFuncSetAttribute(down_all, cudaFuncAttributeMaxDynamicSharedMemorySize, gemm_smem);
        int dev = 0;
        if (cudaGetDevice(&dev) != cudaSuccess) dev = 0;
        int sms = 0;
        if (cudaDeviceGetAttribute(&sms, cudaDevAttrMultiProcessorCount, dev) != cudaSuccess ||
            sms <= 0 || sms > 1024)
            sms = 148;
        num_sms = sms;
    }

    // launch 0: x -> fp16
    {
        int n4 = (TT * HH) >> 2;
        conv_half_kernel<<<(n4 + 255) / 256, 256>>>((const float4*)x, (__half2*)p_cx, n4);
    }
    // launch 1: all weight transposes
    {
        TJobs J;
        J.src[0] = w_gate; J.dst[0] = (__half*)p_wgT; J.K[0] = HH;  J.N[0] = II;
        J.src[1] = w_up;   J.dst[1] = (__half*)p_wuT; J.K[1] = HH;  J.N[1] = II;
        J.src[2] = w_down; J.dst[2] = (__half*)p_wdT; J.K[2] = II;  J.N[2] = HH;
        J.src[3] = sg_w;   J.dst[3] = (__half*)p_sgT; J.K[3] = HH;  J.N[3] = ISH;
        J.src[4] = su_w;   J.dst[4] = (__half*)p_suT; J.K[4] = HH;  J.N[4] = ISH;
        J.src[5] = sd_w;   J.dst[5] = (__half*)p_sdT; J.K[5] = ISH; J.N[5] = HH;
        int mats[6] = {EE, EE, EE, 1, 1, 1};
        int total = 0;
        for (int j = 0; j < 6; j++) {
            J.base[j] = total;
            total += (J.N[j] / 32) * (J.K[j] / 64) * mats[j];
        }
        J.base[6] = total;
        trans_all_kernel<<<total, 256>>>(J);
    }
    // launch 2-4: routing + schedule
    reset_cnt_kernel<<<1, 32>>>((int*)p_cnt);
    router_kernel<<<TT / 8, 256>>>(x, gate_w, gate_b,
                                   (int*)p_ids, (int*)p_cnt,
                                   (int*)p_etok, (float*)p_ewt);
    sched_kernel<<<1, 32>>>((const int*)p_cnt, (int*)p_sched, (int*)p_ctr);

    // launch 5: persistent gate+up (routed + shared)   <- ncu -s 5 target
    gateup_all<<<num_sms, 256, gemm_smem>>>(
        (const __half*)p_cx, (const int*)p_etok,
        (const __half*)p_wgT, (const __half*)p_wuT,
        (const __half*)p_sgT, (const __half*)p_suT,
        (__half*)p_hbuf, (__half*)p_shbuf,
        (const int*)p_sched, (int*)p_ctr);

    // launch 6: zero output, launch 7: persistent down (routed + shared)
    {
        int n4 = (TT * HH) >> 2;
        zero_out_kernel<<<(n4 + 255) / 256, 256>>>((float4*)out, n4);
    }
    down_all<<<num_sms, 256, gemm_smem>>>(
        (const int*)p_etok, (const float*)p_ewt,
        (const __half*)p_wdT, (const __half*)p_sdT,
        (const __half*)p_hbuf, (const __half*)p_shbuf,
        out, (const int*)p_sched, (int*)p_ctr);

    // tail: topk_ids (value-cast), if present in out buffer
    long long main_sz = (long long)TT * HH;
    if ((long long)out_size > main_sz) {
        long long tail = (long long)out_size - main_sz;
        int n = (int)((tail < (long long)TT * TOPK) ? tail : (long long)TT * TOPK);
        ids_to_float_kernel<<<(n + 255) / 256, 256>>>((const int*)p_ids, out + main_sz, n);
    }
}